// round 3
// baseline (speedup 1.0000x reference)
#include <cuda_runtime.h>
#include <cstdint>

#define N_NODES 50000
#define N_EDGES 1600000
#define D_FEAT  512
#define UNITS   512

// Scratch (static __device__ globals — no runtime allocation):
__device__ float g_h[(size_t)N_NODES * UNITS];   // h = X @ W, 102.4 MB
__device__ int   g_src[N_EDGES];                 // normalized int32 indices
__device__ int   g_dst[N_EDGES];
__device__ int   g_is64;                         // dtype flag

// ---------------------------------------------------------------------------
// Kernel 0a: detect whether edge index buffers are int64 or int32.
// If the buffer is true int64, every value's high word is 0 and the low word
// is < N_NODES. If it's int32 read as int64, sampled "values" combine two
// random node ids and blow the range with probability ~1.
// ---------------------------------------------------------------------------
__global__ void detect_kernel(const void* src_raw)
{
    const long long* p = (const long long*)src_raw;
    int ok64 = 1;
    for (int i = 0; i < 64; i++) {
        long long v = p[i];
        if (v < 0 || v >= N_NODES) { ok64 = 0; break; }
    }
    g_is64 = ok64;
}

// ---------------------------------------------------------------------------
// Kernel 0b: normalize indices to int32 scratch.
// ---------------------------------------------------------------------------
__global__ __launch_bounds__(256) void convert_kernel(
    const void* __restrict__ src_raw,
    const void* __restrict__ dst_raw)
{
    const int is64 = g_is64;
    for (int i = blockIdx.x * blockDim.x + threadIdx.x;
         i < N_EDGES;
         i += gridDim.x * blockDim.x) {
        if (is64) {
            g_src[i] = (int)((const long long*)src_raw)[i];
            g_dst[i] = (int)((const long long*)dst_raw)[i];
        } else {
            g_src[i] = ((const int*)src_raw)[i];
            g_dst[i] = ((const int*)dst_raw)[i];
        }
    }
}

// ---------------------------------------------------------------------------
// Kernel 1: h = X @ W   (M=50000, K=512, N=512), fp32, 128x128x8 tiles,
// 256 threads, 8x8 register micro-tile per thread.
// ---------------------------------------------------------------------------
#define BM 128
#define BN 128
#define BK 8

__global__ __launch_bounds__(256) void gemm_kernel(
    const float* __restrict__ A,   // [N_NODES, 512] row-major
    const float* __restrict__ B)   // [512, 512] row-major
{
    __shared__ float As[BK][BM];
    __shared__ float Bs[BK][BN];

    const int bx = blockIdx.x;            // N tile: 0..3
    const int by = blockIdx.y;            // M tile: 0..390
    const int tid = threadIdx.x;

    const int aRow = tid >> 1;            // 0..127
    const int aK   = (tid & 1) * 4;       // 0 or 4
    const int bRow = tid >> 5;            // 0..7
    const int bCol = (tid & 31) * 4;      // 0..124

    const int tx = tid & 15;              // col group 0..15
    const int ty = tid >> 4;              // row group 0..15

    const int rowBase = by * BM;

    float acc[8][8];
#pragma unroll
    for (int i = 0; i < 8; i++)
#pragma unroll
        for (int j = 0; j < 8; j++) acc[i][j] = 0.0f;

    for (int k0 = 0; k0 < D_FEAT; k0 += BK) {
        const int gRow = rowBase + aRow;
        float4 a4 = make_float4(0.f, 0.f, 0.f, 0.f);
        if (gRow < N_NODES)
            a4 = *(const float4*)(A + (size_t)gRow * D_FEAT + k0 + aK);
        As[aK + 0][aRow] = a4.x;
        As[aK + 1][aRow] = a4.y;
        As[aK + 2][aRow] = a4.z;
        As[aK + 3][aRow] = a4.w;

        const float4 b4 = *(const float4*)(B + (size_t)(k0 + bRow) * UNITS + bx * BN + bCol);
        *(float4*)&Bs[bRow][bCol] = b4;

        __syncthreads();

#pragma unroll
        for (int k = 0; k < BK; k++) {
            float ra[8], rb[8];
#pragma unroll
            for (int i = 0; i < 8; i++) ra[i] = As[k][ty * 8 + i];
#pragma unroll
            for (int j = 0; j < 8; j++) rb[j] = Bs[k][tx * 8 + j];
#pragma unroll
            for (int i = 0; i < 8; i++)
#pragma unroll
                for (int j = 0; j < 8; j++)
                    acc[i][j] += ra[i] * rb[j];
        }
        __syncthreads();
    }

#pragma unroll
    for (int i = 0; i < 8; i++) {
        const int gRow = rowBase + ty * 8 + i;
        if (gRow < N_NODES) {
            float4* cp = (float4*)(g_h + (size_t)gRow * UNITS + bx * BN + tx * 8);
            cp[0] = make_float4(acc[i][0], acc[i][1], acc[i][2], acc[i][3]);
            cp[1] = make_float4(acc[i][4], acc[i][5], acc[i][6], acc[i][7]);
        }
    }
}

// ---------------------------------------------------------------------------
// Kernel 2: edge scatter.  out[dst] += w * h[src]
// blockDim = (128, 2): 128 threads per edge (one float4 each), 2 edges/block.
// ---------------------------------------------------------------------------
__global__ __launch_bounds__(256) void scatter_kernel(
    const float* __restrict__ edge_weight,
    float* __restrict__ out)
{
    const int e = blockIdx.x * blockDim.y + threadIdx.y;
    if (e >= N_EDGES) return;

    const int s = g_src[e];
    const int d = g_dst[e];
    const float w = edge_weight[e];

    const float4* __restrict__ hrow = (const float4*)(g_h + (size_t)s * UNITS);
    float* __restrict__ orow = out + (size_t)d * UNITS;

    const int c = threadIdx.x;            // 0..127 float4s = 512 cols
    const float4 v = __ldg(&hrow[c]);
    atomicAdd(orow + 4 * c + 0, v.x * w);
    atomicAdd(orow + 4 * c + 1, v.y * w);
    atomicAdd(orow + 4 * c + 2, v.z * w);
    atomicAdd(orow + 4 * c + 3, v.w * w);
}

// ---------------------------------------------------------------------------
// Kernel 3: epilogue out = relu(out + bias), vectorized float4, grid-stride.
// ---------------------------------------------------------------------------
__global__ __launch_bounds__(256) void epilogue_kernel(
    float* __restrict__ out,
    const float* __restrict__ bias)
{
    const size_t total4 = (size_t)N_NODES * UNITS / 4;
    const float4* __restrict__ b4 = (const float4*)bias;
    float4* __restrict__ o4 = (float4*)out;

    for (size_t i = (size_t)blockIdx.x * blockDim.x + threadIdx.x;
         i < total4;
         i += (size_t)gridDim.x * blockDim.x) {
        float4 v = o4[i];
        const float4 b = b4[i & (UNITS / 4 - 1)];
        v.x = fmaxf(v.x + b.x, 0.0f);
        v.y = fmaxf(v.y + b.y, 0.0f);
        v.z = fmaxf(v.z + b.z, 0.0f);
        v.w = fmaxf(v.w + b.w, 0.0f);
        o4[i] = v;
    }
}

// ---------------------------------------------------------------------------
extern "C" void kernel_launch(void* const* d_in, const int* in_sizes, int n_in,
                              void* d_out, int out_size)
{
    const float* X    = (const float*)d_in[0];   // [50000, 512]
    const float* W    = (const float*)d_in[1];   // [512, 512]
    const float* bias = (const float*)d_in[2];   // [512]
    const float* ew   = (const float*)d_in[3];   // [1.6M]
    const void*  es   = d_in[4];                 // [1.6M] int32 OR int64
    const void*  ed   = d_in[5];                 // [1.6M] int32 OR int64
    float* out = (float*)d_out;                  // [50000, 512]

    // 0) normalize edge indices to int32
    detect_kernel<<<1, 1>>>(es);
    convert_kernel<<<1024, 256>>>(es, ed);

    // 1) h = X @ W
    dim3 gemm_grid(UNITS / BN, (N_NODES + BM - 1) / BM);
    gemm_kernel<<<gemm_grid, 256>>>(X, W);

    // 2) zero output accumulator
    cudaMemsetAsync(d_out, 0, (size_t)out_size * sizeof(float));

    // 3) scatter: out[dst] += w * h[src]
    dim3 sc_block(128, 2);
    dim3 sc_grid((N_EDGES + 2 - 1) / 2);
    scatter_kernel<<<sc_grid, sc_block>>>(ew, out);

    // 4) out = relu(out + bias)
    epilogue_kernel<<<1184, 256>>>(out, bias);
}

// round 4
// speedup vs baseline: 2.7557x; 2.7557x over previous
#include <cuda_runtime.h>
#include <cstdint>

#define N_NODES 50000
#define N_EDGES 1600000
#define D_FEAT  512
#define UNITS   512

// Scratch (static __device__ globals — no runtime allocation):
__device__ float g_h[(size_t)N_NODES * UNITS];   // h = X @ W, 102.4 MB
__device__ int   g_src[N_EDGES];
__device__ int   g_dst[N_EDGES];
__device__ int   g_deg[N_NODES];                 // dst histogram
__device__ int   g_cursor[N_NODES];              // placement cursors
__device__ int   g_off[N_NODES + 1];             // CSR offsets
__device__ int2  g_sorted[N_EDGES];              // (src, weight-bits) by dst
__device__ int   g_is64;

// ---------------------------------------------------------------------------
// Kernel 0a: detect int64 vs int32 edge-index buffers.
// ---------------------------------------------------------------------------
__global__ void detect_kernel(const void* src_raw)
{
    const long long* p = (const long long*)src_raw;
    int ok64 = 1;
    for (int i = 0; i < 64; i++) {
        long long v = p[i];
        if (v < 0 || v >= N_NODES) { ok64 = 0; break; }
    }
    g_is64 = ok64;
}

// ---------------------------------------------------------------------------
// Kernel 0b: zero histogram + cursors.
// ---------------------------------------------------------------------------
__global__ __launch_bounds__(256) void zero_kernel()
{
    for (int i = blockIdx.x * blockDim.x + threadIdx.x;
         i < N_NODES;
         i += gridDim.x * blockDim.x) {
        g_deg[i] = 0;
        g_cursor[i] = 0;
    }
}

// ---------------------------------------------------------------------------
// Kernel 0c: normalize indices to int32 + build dst histogram.
// ---------------------------------------------------------------------------
__global__ __launch_bounds__(256) void convert_hist_kernel(
    const void* __restrict__ src_raw,
    const void* __restrict__ dst_raw)
{
    const int is64 = g_is64;
    for (int i = blockIdx.x * blockDim.x + threadIdx.x;
         i < N_EDGES;
         i += gridDim.x * blockDim.x) {
        int s, d;
        if (is64) {
            s = (int)((const long long*)src_raw)[i];
            d = (int)((const long long*)dst_raw)[i];
        } else {
            s = ((const int*)src_raw)[i];
            d = ((const int*)dst_raw)[i];
        }
        g_src[i] = s;
        g_dst[i] = d;
        atomicAdd(&g_deg[d], 1);
    }
}

// ---------------------------------------------------------------------------
// Kernel 0d: exclusive scan of g_deg -> g_off. Single block, 1024 threads.
// ---------------------------------------------------------------------------
__global__ __launch_bounds__(1024) void scan_kernel()
{
    __shared__ int partial[1024];
    const int T = 1024;
    const int tid = threadIdx.x;
    const int chunk = (N_NODES + T - 1) / T;   // 49
    const int start = tid * chunk;
    const int end = min(start + chunk, N_NODES);

    int sum = 0;
    for (int i = start; i < end; i++) sum += g_deg[i];
    partial[tid] = sum;
    __syncthreads();

    // inclusive Hillis-Steele scan over partials
    for (int off = 1; off < T; off <<= 1) {
        int v = (tid >= off) ? partial[tid - off] : 0;
        __syncthreads();
        partial[tid] += v;
        __syncthreads();
    }

    int base = (tid == 0) ? 0 : partial[tid - 1];
    for (int i = start; i < end; i++) {
        g_off[i] = base;
        base += g_deg[i];
    }
    if (tid == T - 1) g_off[N_NODES] = base;
}

// ---------------------------------------------------------------------------
// Kernel 0e: place (src, weight) pairs into dst-sorted order.
// ---------------------------------------------------------------------------
__global__ __launch_bounds__(256) void place_kernel(
    const float* __restrict__ edge_weight)
{
    for (int i = blockIdx.x * blockDim.x + threadIdx.x;
         i < N_EDGES;
         i += gridDim.x * blockDim.x) {
        const int d = g_dst[i];
        const int pos = g_off[d] + atomicAdd(&g_cursor[d], 1);
        g_sorted[pos] = make_int2(g_src[i], __float_as_int(edge_weight[i]));
    }
}

// ---------------------------------------------------------------------------
// Kernel 1: h = X @ W   (M=50000, K=512, N=512), fp32, 128x128x8 tiles.
// ---------------------------------------------------------------------------
#define BM 128
#define BN 128
#define BK 8

__global__ __launch_bounds__(256) void gemm_kernel(
    const float* __restrict__ A,
    const float* __restrict__ B)
{
    __shared__ float As[BK][BM];
    __shared__ float Bs[BK][BN];

    const int bx = blockIdx.x;
    const int by = blockIdx.y;
    const int tid = threadIdx.x;

    const int aRow = tid >> 1;
    const int aK   = (tid & 1) * 4;
    const int bRow = tid >> 5;
    const int bCol = (tid & 31) * 4;

    const int tx = tid & 15;
    const int ty = tid >> 4;

    const int rowBase = by * BM;

    float acc[8][8];
#pragma unroll
    for (int i = 0; i < 8; i++)
#pragma unroll
        for (int j = 0; j < 8; j++) acc[i][j] = 0.0f;

    for (int k0 = 0; k0 < D_FEAT; k0 += BK) {
        const int gRow = rowBase + aRow;
        float4 a4 = make_float4(0.f, 0.f, 0.f, 0.f);
        if (gRow < N_NODES)
            a4 = *(const float4*)(A + (size_t)gRow * D_FEAT + k0 + aK);
        As[aK + 0][aRow] = a4.x;
        As[aK + 1][aRow] = a4.y;
        As[aK + 2][aRow] = a4.z;
        As[aK + 3][aRow] = a4.w;

        const float4 b4 = *(const float4*)(B + (size_t)(k0 + bRow) * UNITS + bx * BN + bCol);
        *(float4*)&Bs[bRow][bCol] = b4;

        __syncthreads();

#pragma unroll
        for (int k = 0; k < BK; k++) {
            float ra[8], rb[8];
#pragma unroll
            for (int i = 0; i < 8; i++) ra[i] = As[k][ty * 8 + i];
#pragma unroll
            for (int j = 0; j < 8; j++) rb[j] = Bs[k][tx * 8 + j];
#pragma unroll
            for (int i = 0; i < 8; i++)
#pragma unroll
                for (int j = 0; j < 8; j++)
                    acc[i][j] += ra[i] * rb[j];
        }
        __syncthreads();
    }

#pragma unroll
    for (int i = 0; i < 8; i++) {
        const int gRow = rowBase + ty * 8 + i;
        if (gRow < N_NODES) {
            float4* cp = (float4*)(g_h + (size_t)gRow * UNITS + bx * BN + tx * 8);
            cp[0] = make_float4(acc[i][0], acc[i][1], acc[i][2], acc[i][3]);
            cp[1] = make_float4(acc[i][4], acc[i][5], acc[i][6], acc[i][7]);
        }
    }
}

// ---------------------------------------------------------------------------
// Kernel 2: aggregate. One block per dst row; 128 threads, float4 acc each.
// out[d] = relu(sum_e w_e * h[src_e] + bias). No atomics; single write.
// ---------------------------------------------------------------------------
__global__ __launch_bounds__(128) void aggregate_kernel(
    const float* __restrict__ bias,
    float* __restrict__ out)
{
    const int d = blockIdx.x;
    const int c = threadIdx.x;                    // 0..127 -> float4 lane
    const int beg = g_off[d];
    const int end = g_off[d + 1];

    const float4* __restrict__ h4 = (const float4*)g_h;

    float4 acc = make_float4(0.f, 0.f, 0.f, 0.f);

    int e = beg;
    for (; e + 1 < end; e += 2) {
        const int2 sw0 = g_sorted[e];
        const int2 sw1 = g_sorted[e + 1];
        const float4 v0 = __ldg(&h4[(size_t)sw0.x * (UNITS / 4) + c]);
        const float4 v1 = __ldg(&h4[(size_t)sw1.x * (UNITS / 4) + c]);
        const float w0 = __int_as_float(sw0.y);
        const float w1 = __int_as_float(sw1.y);
        acc.x = fmaf(w0, v0.x, acc.x); acc.y = fmaf(w0, v0.y, acc.y);
        acc.z = fmaf(w0, v0.z, acc.z); acc.w = fmaf(w0, v0.w, acc.w);
        acc.x = fmaf(w1, v1.x, acc.x); acc.y = fmaf(w1, v1.y, acc.y);
        acc.z = fmaf(w1, v1.z, acc.z); acc.w = fmaf(w1, v1.w, acc.w);
    }
    if (e < end) {
        const int2 sw = g_sorted[e];
        const float4 v = __ldg(&h4[(size_t)sw.x * (UNITS / 4) + c]);
        const float w = __int_as_float(sw.y);
        acc.x = fmaf(w, v.x, acc.x); acc.y = fmaf(w, v.y, acc.y);
        acc.z = fmaf(w, v.z, acc.z); acc.w = fmaf(w, v.w, acc.w);
    }

    const float4 b = ((const float4*)bias)[c];
    float4 r;
    r.x = fmaxf(acc.x + b.x, 0.0f);
    r.y = fmaxf(acc.y + b.y, 0.0f);
    r.z = fmaxf(acc.z + b.z, 0.0f);
    r.w = fmaxf(acc.w + b.w, 0.0f);
    ((float4*)out)[(size_t)d * (UNITS / 4) + c] = r;
}

// ---------------------------------------------------------------------------
extern "C" void kernel_launch(void* const* d_in, const int* in_sizes, int n_in,
                              void* d_out, int out_size)
{
    const float* X    = (const float*)d_in[0];
    const float* W    = (const float*)d_in[1];
    const float* bias = (const float*)d_in[2];
    const float* ew   = (const float*)d_in[3];
    const void*  es   = d_in[4];
    const void*  ed   = d_in[5];
    float* out = (float*)d_out;

    // 0) CSR build: detect dtype, zero, convert+histogram, scan, place
    detect_kernel<<<1, 1>>>(es);
    zero_kernel<<<64, 256>>>();
    convert_hist_kernel<<<1024, 256>>>(es, ed);
    scan_kernel<<<1, 1024>>>();
    place_kernel<<<1024, 256>>>(ew);

    // 1) h = X @ W
    dim3 gemm_grid(UNITS / BN, (N_NODES + BM - 1) / BM);
    gemm_kernel<<<gemm_grid, 256>>>(X, W);

    // 2) aggregate with fused bias + ReLU (writes every output row exactly once)
    aggregate_kernel<<<N_NODES, 128>>>(bias, out);
}

// round 6
// speedup vs baseline: 4.0093x; 1.4549x over previous
#include <cuda_runtime.h>
#include <cuda_bf16.h>
#include <cstdint>

#define N_NODES 50000
#define N_PAD   50048            // 391 * 128
#define N_EDGES 1600000
#define D_FEAT  512
#define UNITS   512

// ---------------- static device scratch (no runtime allocation) ----------
__device__ float           g_h[(size_t)N_PAD * UNITS];       // h = X @ W
__device__ __nv_bfloat16   g_Ah[(size_t)N_PAD * D_FEAT];     // bf16 split of X
__device__ __nv_bfloat16   g_Al[(size_t)N_PAD * D_FEAT];
__device__ __nv_bfloat16   g_Wh[(size_t)UNITS * D_FEAT];     // W^T split: [n][k]
__device__ __nv_bfloat16   g_Wl[(size_t)UNITS * D_FEAT];
__device__ int   g_src[N_EDGES];
__device__ int   g_dst[N_EDGES];
__device__ int   g_deg[N_NODES];
__device__ int   g_cursor[N_NODES];
__device__ int   g_off[N_NODES + 1];
__device__ int2  g_sorted[N_EDGES];
__device__ int   g_is64;

// ---------------- helpers ------------------------------------------------
__device__ __forceinline__ uint32_t smem_u32(const void* p) {
    uint32_t a;
    asm("{ .reg .u64 t; cvta.to.shared.u64 t, %1; cvt.u32.u64 %0, t; }"
        : "=r"(a) : "l"(p));
    return a;
}
__device__ __forceinline__ void cp_async16(uint32_t dst, const void* src) {
    asm volatile("cp.async.cg.shared.global [%0], [%1], 16;" :: "r"(dst), "l"(src));
}
#define CP_COMMIT() asm volatile("cp.async.commit_group;" ::: "memory")
#define CP_WAIT(n)  asm volatile("cp.async.wait_group %0;" :: "n"(n) : "memory")

#define LDMATRIX_X4(r0, r1, r2, r3, addr) \
    asm volatile("ldmatrix.sync.aligned.m8n8.x4.shared.b16 {%0,%1,%2,%3}, [%4];" \
        : "=r"(r0), "=r"(r1), "=r"(r2), "=r"(r3) : "r"(addr))

__device__ __forceinline__ void mma16816(float* d, const uint32_t* a,
                                         uint32_t b0, uint32_t b1) {
    asm volatile(
        "mma.sync.aligned.m16n8k16.row.col.f32.bf16.bf16.f32 "
        "{%0,%1,%2,%3}, {%4,%5,%6,%7}, {%8,%9}, {%0,%1,%2,%3};"
        : "+f"(d[0]), "+f"(d[1]), "+f"(d[2]), "+f"(d[3])
        : "r"(a[0]), "r"(a[1]), "r"(a[2]), "r"(a[3]), "r"(b0), "r"(b1));
}

// ---------------------------------------------------------------------------
// CSR build kernels (unchanged from round-3 passing version)
// ---------------------------------------------------------------------------
__global__ void detect_kernel(const void* src_raw)
{
    const long long* p = (const long long*)src_raw;
    int ok64 = 1;
    for (int i = 0; i < 64; i++) {
        long long v = p[i];
        if (v < 0 || v >= N_NODES) { ok64 = 0; break; }
    }
    g_is64 = ok64;
}

__global__ __launch_bounds__(256) void zero_kernel()
{
    for (int i = blockIdx.x * blockDim.x + threadIdx.x;
         i < N_NODES; i += gridDim.x * blockDim.x) {
        g_deg[i] = 0;
        g_cursor[i] = 0;
    }
}

__global__ __launch_bounds__(256) void convert_hist_kernel(
    const void* __restrict__ src_raw, const void* __restrict__ dst_raw)
{
    const int is64 = g_is64;
    for (int i = blockIdx.x * blockDim.x + threadIdx.x;
         i < N_EDGES; i += gridDim.x * blockDim.x) {
        int s, d;
        if (is64) {
            s = (int)((const long long*)src_raw)[i];
            d = (int)((const long long*)dst_raw)[i];
        } else {
            s = ((const int*)src_raw)[i];
            d = ((const int*)dst_raw)[i];
        }
        g_src[i] = s;
        g_dst[i] = d;
        atomicAdd(&g_deg[d], 1);
    }
}

__global__ __launch_bounds__(1024) void scan_kernel()
{
    __shared__ int partial[1024];
    const int T = 1024;
    const int tid = threadIdx.x;
    const int chunk = (N_NODES + T - 1) / T;
    const int start = tid * chunk;
    const int end = min(start + chunk, N_NODES);

    int sum = 0;
    for (int i = start; i < end; i++) sum += g_deg[i];
    partial[tid] = sum;
    __syncthreads();
    for (int off = 1; off < T; off <<= 1) {
        int v = (tid >= off) ? partial[tid - off] : 0;
        __syncthreads();
        partial[tid] += v;
        __syncthreads();
    }
    int base = (tid == 0) ? 0 : partial[tid - 1];
    for (int i = start; i < end; i++) {
        g_off[i] = base;
        base += g_deg[i];
    }
    if (tid == T - 1) g_off[N_NODES] = base;
}

__global__ __launch_bounds__(256) void place_kernel(const float* __restrict__ ew)
{
    for (int i = blockIdx.x * blockDim.x + threadIdx.x;
         i < N_EDGES; i += gridDim.x * blockDim.x) {
        const int d = g_dst[i];
        const int pos = g_off[d] + atomicAdd(&g_cursor[d], 1);
        g_sorted[pos] = make_int2(g_src[i], __float_as_int(ew[i]));
    }
}

// ---------------------------------------------------------------------------
// Prep: bf16 split of X (padded rows zeroed) and of W^T.
// ---------------------------------------------------------------------------
__global__ __launch_bounds__(256) void split_X_kernel(const float* __restrict__ X)
{
    const size_t total4 = (size_t)N_PAD * D_FEAT / 4;
    const size_t valid4 = (size_t)N_NODES * D_FEAT / 4;
    for (size_t i = (size_t)blockIdx.x * blockDim.x + threadIdx.x;
         i < total4; i += (size_t)gridDim.x * blockDim.x) {
        float4 x = (i < valid4) ? ((const float4*)X)[i] : make_float4(0.f, 0.f, 0.f, 0.f);
        __nv_bfloat16 h0 = __float2bfloat16(x.x), h1 = __float2bfloat16(x.y);
        __nv_bfloat16 h2 = __float2bfloat16(x.z), h3 = __float2bfloat16(x.w);
        __nv_bfloat16 l0 = __float2bfloat16(x.x - __bfloat162float(h0));
        __nv_bfloat16 l1 = __float2bfloat16(x.y - __bfloat162float(h1));
        __nv_bfloat16 l2 = __float2bfloat16(x.z - __bfloat162float(h2));
        __nv_bfloat16 l3 = __float2bfloat16(x.w - __bfloat162float(h3));
        __nv_bfloat162 hp0 = {h0, h1}, hp1 = {h2, h3};
        __nv_bfloat162 lp0 = {l0, l1}, lp1 = {l2, l3};
        ((uint2*)g_Ah)[i] = make_uint2(*(uint32_t*)&hp0, *(uint32_t*)&hp1);
        ((uint2*)g_Al)[i] = make_uint2(*(uint32_t*)&lp0, *(uint32_t*)&lp1);
    }
}

__global__ __launch_bounds__(256) void split_W_kernel(const float* __restrict__ W)
{
    for (int i = blockIdx.x * blockDim.x + threadIdx.x;
         i < UNITS * D_FEAT; i += gridDim.x * blockDim.x) {
        const int n = i >> 9, k = i & 511;
        const float w = W[(size_t)k * UNITS + n];
        const __nv_bfloat16 h = __float2bfloat16(w);
        const __nv_bfloat16 l = __float2bfloat16(w - __bfloat162float(h));
        g_Wh[i] = h;
        g_Wl[i] = l;
    }
}

// ---------------------------------------------------------------------------
// bf16 mma.sync GEMM: h = Ah*Wh + Ah*Wl + Al*Wh  (fp32 accumulate)
// CTA tile 128x128x32, 8 warps (2x4), warp tile 64x32, double-buffered cp.async.
// ---------------------------------------------------------------------------
#define BM 128
#define BN 128
#define BK 32
#define PAD 40                      // row pitch (elems); 80B, conflict-free ldmatrix
#define N_ITERS 48                  // 3 terms * (512/32)

__global__ __launch_bounds__(256) void gemm_mma_kernel()
{
    __shared__ __align__(16) __nv_bfloat16 As[2][BM][PAD];
    __shared__ __align__(16) __nv_bfloat16 Bs[2][BN][PAD];

    const int tid = threadIdx.x;
    const int wid = tid >> 5, lid = tid & 31;
    const int wr = wid >> 2, wc = wid & 3;     // warp row (0-1), warp col (0-3)
    const int bx = blockIdx.x;                 // N tile: 0..3
    const int by = blockIdx.y;                 // M tile: 0..390

    const uint32_t aSm = smem_u32(As);
    const uint32_t bSm = smem_u32(Bs);
    const uint32_t ABUF = BM * PAD * 2;        // bytes per A buffer
    const uint32_t BBUF = BN * PAD * 2;

    const __nv_bfloat16* Abase[3] = {g_Ah, g_Ah, g_Al};
    const __nv_bfloat16* Bbase[3] = {g_Wh, g_Wl, g_Wh};

    float acc[4][4][4];
#pragma unroll
    for (int mi = 0; mi < 4; mi++)
#pragma unroll
        for (int nj = 0; nj < 4; nj++)
#pragma unroll
            for (int q = 0; q < 4; q++) acc[mi][nj][q] = 0.0f;

    // chunk loader: A/B tile rows split into 16B pieces; 2 per thread each.
    const int cr0 = tid >> 2;                  // chunk row for piece 0 (0..63)
    const int cc  = (tid & 3) * 8;             // elem col {0,8,16,24}

#define LOAD_TILE(it, buf) do {                                                   \
        const int _t = (it) >> 4;                                                 \
        const int _k0 = ((it) & 15) * BK;                                         \
        const __nv_bfloat16* _Ap = Abase[_t] + (size_t)(by * BM) * D_FEAT + _k0;  \
        const __nv_bfloat16* _Bp = Bbase[_t] + (size_t)(bx * BN) * D_FEAT + _k0;  \
        cp_async16(aSm + (buf) * ABUF + (uint32_t)(cr0 * PAD + cc) * 2,           \
                   _Ap + (size_t)cr0 * D_FEAT + cc);                              \
        cp_async16(aSm + (buf) * ABUF + (uint32_t)((cr0 + 64) * PAD + cc) * 2,    \
                   _Ap + (size_t)(cr0 + 64) * D_FEAT + cc);                       \
        cp_async16(bSm + (buf) * BBUF + (uint32_t)(cr0 * PAD + cc) * 2,           \
                   _Bp + (size_t)cr0 * D_FEAT + cc);                              \
        cp_async16(bSm + (buf) * BBUF + (uint32_t)((cr0 + 64) * PAD + cc) * 2,    \
                   _Bp + (size_t)(cr0 + 64) * D_FEAT + cc);                       \
        CP_COMMIT();                                                              \
    } while (0)

    LOAD_TILE(0, 0);

    const int lrow = lid & 15;                 // ldmatrix row within 16
    const int lcol8 = (lid >> 4) * 8;          // 0 or 8

#pragma unroll 1
    for (int it = 0; it < N_ITERS; it++) {
        const int b = it & 1;
        if (it + 1 < N_ITERS) {
            LOAD_TILE(it + 1, b ^ 1);
            CP_WAIT(1);
        } else {
            CP_WAIT(0);
        }
        __syncthreads();

#pragma unroll
        for (int ks = 0; ks < BK; ks += 16) {
            uint32_t af[4][4];
#pragma unroll
            for (int mi = 0; mi < 4; mi++) {
                const uint32_t addr = aSm + b * ABUF +
                    (uint32_t)((wr * 64 + mi * 16 + lrow) * PAD + ks + lcol8) * 2;
                LDMATRIX_X4(af[mi][0], af[mi][1], af[mi][2], af[mi][3], addr);
            }
            uint32_t bf[2][4];
#pragma unroll
            for (int nh = 0; nh < 2; nh++) {
                const uint32_t addr = bSm + b * BBUF +
                    (uint32_t)((wc * 32 + nh * 16 + lrow) * PAD + ks + lcol8) * 2;
                LDMATRIX_X4(bf[nh][0], bf[nh][1], bf[nh][2], bf[nh][3], addr);
            }
#pragma unroll
            for (int mi = 0; mi < 4; mi++)
#pragma unroll
                for (int nj = 0; nj < 4; nj++) {
                    const uint32_t b0 = bf[nj >> 1][(nj & 1)];
                    const uint32_t b1 = bf[nj >> 1][(nj & 1) + 2];
                    mma16816(acc[mi][nj], af[mi], b0, b1);
                }
        }
        __syncthreads();
    }

    // epilogue: write fp32 accumulators to g_h
    const int qrow = lid >> 2;                 // 0..7
    const int qcol = (lid & 3) * 2;            // 0,2,4,6
#pragma unroll
    for (int mi = 0; mi < 4; mi++) {
        const size_t r0 = (size_t)by * BM + wr * 64 + mi * 16 + qrow;
#pragma unroll
        for (int nj = 0; nj < 4; nj++) {
            const int c0 = bx * BN + wc * 32 + nj * 8 + qcol;
            *(float2*)(g_h + r0 * UNITS + c0) = make_float2(acc[mi][nj][0], acc[mi][nj][1]);
            *(float2*)(g_h + (r0 + 8) * UNITS + c0) = make_float2(acc[mi][nj][2], acc[mi][nj][3]);
        }
    }
}

// ---------------------------------------------------------------------------
// Aggregate: one block per dst row; fused bias + ReLU. No atomics.
// ---------------------------------------------------------------------------
__global__ __launch_bounds__(128) void aggregate_kernel(
    const float* __restrict__ bias, float* __restrict__ out)
{
    const int d = blockIdx.x;
    const int c = threadIdx.x;
    const int beg = g_off[d];
    const int end = g_off[d + 1];

    const float4* __restrict__ h4 = (const float4*)g_h;
    float4 acc = make_float4(0.f, 0.f, 0.f, 0.f);

    int e = beg;
    for (; e + 1 < end; e += 2) {
        const int2 sw0 = g_sorted[e];
        const int2 sw1 = g_sorted[e + 1];
        const float4 v0 = __ldg(&h4[(size_t)sw0.x * (UNITS / 4) + c]);
        const float4 v1 = __ldg(&h4[(size_t)sw1.x * (UNITS / 4) + c]);
        const float w0 = __int_as_float(sw0.y);
        const float w1 = __int_as_float(sw1.y);
        acc.x = fmaf(w0, v0.x, acc.x); acc.y = fmaf(w0, v0.y, acc.y);
        acc.z = fmaf(w0, v0.z, acc.z); acc.w = fmaf(w0, v0.w, acc.w);
        acc.x = fmaf(w1, v1.x, acc.x); acc.y = fmaf(w1, v1.y, acc.y);
        acc.z = fmaf(w1, v1.z, acc.z); acc.w = fmaf(w1, v1.w, acc.w);
    }
    if (e < end) {
        const int2 sw = g_sorted[e];
        const float4 v = __ldg(&h4[(size_t)sw.x * (UNITS / 4) + c]);
        const float w = __int_as_float(sw.y);
        acc.x = fmaf(w, v.x, acc.x); acc.y = fmaf(w, v.y, acc.y);
        acc.z = fmaf(w, v.z, acc.z); acc.w = fmaf(w, v.w, acc.w);
    }

    const float4 b = ((const float4*)bias)[c];
    float4 r;
    r.x = fmaxf(acc.x + b.x, 0.0f);
    r.y = fmaxf(acc.y + b.y, 0.0f);
    r.z = fmaxf(acc.z + b.z, 0.0f);
    r.w = fmaxf(acc.w + b.w, 0.0f);
    ((float4*)out)[(size_t)d * (UNITS / 4) + c] = r;
}

// ---------------------------------------------------------------------------
extern "C" void kernel_launch(void* const* d_in, const int* in_sizes, int n_in,
                              void* d_out, int out_size)
{
    const float* X    = (const float*)d_in[0];
    const float* W    = (const float*)d_in[1];
    const float* bias = (const float*)d_in[2];
    const float* ew   = (const float*)d_in[3];
    const void*  es   = d_in[4];
    const void*  ed   = d_in[5];
    float* out = (float*)d_out;

    // 0) CSR build
    detect_kernel<<<1, 1>>>(es);
    zero_kernel<<<64, 256>>>();
    convert_hist_kernel<<<1024, 256>>>(es, ed);
    scan_kernel<<<1, 1024>>>();
    place_kernel<<<1024, 256>>>(ew);

    // 1) bf16 split prep
    split_X_kernel<<<2048, 256>>>(X);
    split_W_kernel<<<256, 256>>>(W);

    // 2) h = X @ W on tensor cores (bf16 3-term split, fp32 accum)
    dim3 ggrid(UNITS / BN, N_PAD / BM);
    gemm_mma_kernel<<<ggrid, 256>>>();

    // 3) aggregate + bias + ReLU
    aggregate_kernel<<<N_NODES, 128>>>(bias, out);
}

// round 7
// speedup vs baseline: 4.2971x; 1.0718x over previous
#include <cuda_runtime.h>
#include <cuda_bf16.h>
#include <cstdint>

#define N_NODES 50000
#define N_PAD   50048            // 391 * 128
#define N_EDGES 1600000
#define D_FEAT  512
#define UNITS   512

// ---------------- static device scratch (no runtime allocation) ----------
__device__ float           g_h[(size_t)N_PAD * UNITS];       // h = X @ W
__device__ __nv_bfloat16   g_Ah[(size_t)N_PAD * D_FEAT];     // bf16 split of X
__device__ __nv_bfloat16   g_Al[(size_t)N_PAD * D_FEAT];
__device__ __nv_bfloat16   g_Wh[(size_t)UNITS * D_FEAT];     // W^T split: [n][k]
__device__ __nv_bfloat16   g_Wl[(size_t)UNITS * D_FEAT];
__device__ int   g_deg[N_NODES];
__device__ int   g_cursor[N_NODES];
__device__ int   g_off[N_NODES + 1];
__device__ int2  g_sorted[N_EDGES];
__device__ int   g_is64;

#define SCAN_NB 196               // ceil(50000 / 256)
__device__ int g_blk_flag[SCAN_NB];   // 0=invalid 1=aggregate 2=prefix
__device__ int g_blk_agg[SCAN_NB];
__device__ int g_blk_pref[SCAN_NB];

// ---------------- helpers ------------------------------------------------
__device__ __forceinline__ uint32_t smem_u32(const void* p) {
    uint32_t a;
    asm("{ .reg .u64 t; cvta.to.shared.u64 t, %1; cvt.u32.u64 %0, t; }"
        : "=r"(a) : "l"(p));
    return a;
}
__device__ __forceinline__ void cp_async16(uint32_t dst, const void* src) {
    asm volatile("cp.async.cg.shared.global [%0], [%1], 16;" :: "r"(dst), "l"(src));
}
#define CP_COMMIT() asm volatile("cp.async.commit_group;" ::: "memory")
#define CP_WAIT(n)  asm volatile("cp.async.wait_group %0;" :: "n"(n) : "memory")

#define LDMATRIX_X4(r0, r1, r2, r3, addr) \
    asm volatile("ldmatrix.sync.aligned.m8n8.x4.shared.b16 {%0,%1,%2,%3}, [%4];" \
        : "=r"(r0), "=r"(r1), "=r"(r2), "=r"(r3) : "r"(addr))

__device__ __forceinline__ void mma16816(float* d, const uint32_t* a,
                                         uint32_t b0, uint32_t b1) {
    asm volatile(
        "mma.sync.aligned.m16n8k16.row.col.f32.bf16.bf16.f32 "
        "{%0,%1,%2,%3}, {%4,%5,%6,%7}, {%8,%9}, {%0,%1,%2,%3};"
        : "+f"(d[0]), "+f"(d[1]), "+f"(d[2]), "+f"(d[3])
        : "r"(a[0]), "r"(a[1]), "r"(a[2]), "r"(a[3]), "r"(b0), "r"(b1));
}

// ---------------------------------------------------------------------------
// CSR build
// ---------------------------------------------------------------------------
__global__ void detect_kernel(const void* src_raw)
{
    const long long* p = (const long long*)src_raw;
    int ok64 = 1;
    for (int i = 0; i < 64; i++) {
        long long v = p[i];
        if (v < 0 || v >= N_NODES) { ok64 = 0; break; }
    }
    g_is64 = ok64;
}

__global__ __launch_bounds__(256) void zero_kernel()
{
    const int t = blockIdx.x * blockDim.x + threadIdx.x;
    for (int i = t; i < N_NODES; i += gridDim.x * blockDim.x) {
        g_deg[i] = 0;
        g_cursor[i] = 0;
    }
    if (t < SCAN_NB) g_blk_flag[t] = 0;
    if (t == 0) g_off[N_NODES] = N_EDGES;
}

__global__ __launch_bounds__(256) void hist_kernel(const void* __restrict__ dst_raw)
{
    const int is64 = g_is64;
    for (int i = blockIdx.x * blockDim.x + threadIdx.x;
         i < N_EDGES; i += gridDim.x * blockDim.x) {
        const int d = is64 ? (int)((const long long*)dst_raw)[i]
                           : ((const int*)dst_raw)[i];
        atomicAdd(&g_deg[d], 1);
    }
}

// Decoupled-lookback exclusive scan of g_deg -> g_off. 196 blocks x 256.
__global__ __launch_bounds__(256) void scan_lookback_kernel()
{
    __shared__ int warp_sums[8];
    __shared__ int s_total;
    __shared__ int s_base;

    const int b = blockIdx.x;
    const int tid = threadIdx.x;
    const int i = b * 256 + tid;
    const int lane = tid & 31;
    const int w = tid >> 5;

    const int v = (i < N_NODES) ? g_deg[i] : 0;

    // intra-warp inclusive scan
    int incl = v;
#pragma unroll
    for (int o = 1; o < 32; o <<= 1) {
        int t = __shfl_up_sync(0xFFFFFFFFu, incl, o);
        if (lane >= o) incl += t;
    }
    if (lane == 31) warp_sums[w] = incl;
    __syncthreads();

    if (w == 0) {
        int ws = (lane < 8) ? warp_sums[lane] : 0;
        int wincl = ws;
#pragma unroll
        for (int o = 1; o < 8; o <<= 1) {
            int t = __shfl_up_sync(0xFFFFFFFFu, wincl, o);
            if (lane >= o) wincl += t;
        }
        if (lane < 8) warp_sums[lane] = wincl - ws;   // exclusive warp base
        if (lane == 7) s_total = wincl;
    }
    __syncthreads();

    if (tid == 0) {
        volatile int* vflag = g_blk_flag;
        volatile int* vagg  = g_blk_agg;
        volatile int* vpref = g_blk_pref;
        g_blk_agg[b] = s_total;
        __threadfence();
        if (b == 0) {
            g_blk_pref[0] = s_total;
            __threadfence();
            vflag[0] = 2;
            s_base = 0;
        } else {
            vflag[b] = 1;
            int running = 0;
            int p = b - 1;
            while (true) {
                int f;
                do { f = vflag[p]; } while (f == 0);
                if (f == 2) { running += vpref[p]; break; }
                running += vagg[p];
                p--;
            }
            s_base = running;
            g_blk_pref[b] = running + s_total;
            __threadfence();
            vflag[b] = 2;
        }
    }
    __syncthreads();

    if (i < N_NODES)
        g_off[i] = s_base + warp_sums[w] + incl - v;
}

__global__ __launch_bounds__(256) void place_kernel(
    const void* __restrict__ src_raw, const void* __restrict__ dst_raw,
    const float* __restrict__ ew)
{
    const int is64 = g_is64;
    for (int i = blockIdx.x * blockDim.x + threadIdx.x;
         i < N_EDGES; i += gridDim.x * blockDim.x) {
        int s, d;
        if (is64) {
            s = (int)((const long long*)src_raw)[i];
            d = (int)((const long long*)dst_raw)[i];
        } else {
            s = ((const int*)src_raw)[i];
            d = ((const int*)dst_raw)[i];
        }
        const int pos = g_off[d] + atomicAdd(&g_cursor[d], 1);
        g_sorted[pos] = make_int2(s, __float_as_int(ew[i]));
    }
}

// ---------------------------------------------------------------------------
// Prep: bf16 split of X (padded rows zeroed) and of W^T.
// ---------------------------------------------------------------------------
__global__ __launch_bounds__(256) void split_X_kernel(const float* __restrict__ X)
{
    const size_t total4 = (size_t)N_PAD * D_FEAT / 4;
    const size_t valid4 = (size_t)N_NODES * D_FEAT / 4;
    for (size_t i = (size_t)blockIdx.x * blockDim.x + threadIdx.x;
         i < total4; i += (size_t)gridDim.x * blockDim.x) {
        float4 x = (i < valid4) ? ((const float4*)X)[i] : make_float4(0.f, 0.f, 0.f, 0.f);
        __nv_bfloat16 h0 = __float2bfloat16(x.x), h1 = __float2bfloat16(x.y);
        __nv_bfloat16 h2 = __float2bfloat16(x.z), h3 = __float2bfloat16(x.w);
        __nv_bfloat16 l0 = __float2bfloat16(x.x - __bfloat162float(h0));
        __nv_bfloat16 l1 = __float2bfloat16(x.y - __bfloat162float(h1));
        __nv_bfloat16 l2 = __float2bfloat16(x.z - __bfloat162float(h2));
        __nv_bfloat16 l3 = __float2bfloat16(x.w - __bfloat162float(h3));
        __nv_bfloat162 hp0 = {h0, h1}, hp1 = {h2, h3};
        __nv_bfloat162 lp0 = {l0, l1}, lp1 = {l2, l3};
        ((uint2*)g_Ah)[i] = make_uint2(*(uint32_t*)&hp0, *(uint32_t*)&hp1);
        ((uint2*)g_Al)[i] = make_uint2(*(uint32_t*)&lp0, *(uint32_t*)&lp1);
    }
}

__global__ __launch_bounds__(256) void split_W_kernel(const float* __restrict__ W)
{
    for (int i = blockIdx.x * blockDim.x + threadIdx.x;
         i < UNITS * D_FEAT; i += gridDim.x * blockDim.x) {
        const int n = i >> 9, k = i & 511;
        const float w = W[(size_t)k * UNITS + n];
        const __nv_bfloat16 h = __float2bfloat16(w);
        const __nv_bfloat16 l = __float2bfloat16(w - __bfloat162float(h));
        g_Wh[i] = h;
        g_Wl[i] = l;
    }
}

// ---------------------------------------------------------------------------
// bf16 mma.sync GEMM: h = Ah*Wh + Ah*Wl + Al*Wh  (fp32 accumulate)
// CTA tile 128x256x32, 8 warps (2x4), warp tile 64x64, double-buffered cp.async.
// ---------------------------------------------------------------------------
#define BM 128
#define BN 256
#define BK 32
#define PAD 40                      // row pitch elems; 80B -> conflict-free ldmatrix
#define ABUF (BM * PAD * 2)         // 10240 B
#define BBUF (BN * PAD * 2)         // 20480 B
#define GSM  (2 * (ABUF + BBUF))    // 61440 B dynamic smem
#define N_ITERS 48                  // 3 terms * (512/32)

__global__ __launch_bounds__(256, 1) void gemm_mma_kernel()
{
    extern __shared__ __align__(16) char sm[];
    const uint32_t aSm = smem_u32(sm);
    const uint32_t bSm = aSm + 2 * ABUF;

    const int tid = threadIdx.x;
    const int wid = tid >> 5, lid = tid & 31;
    const int wr = wid >> 2, wc = wid & 3;     // warp grid 2 x 4
    const int bx = blockIdx.x;                 // N tile: 0..1
    const int by = blockIdx.y;                 // M tile: 0..390

    const __nv_bfloat16* Abase[3] = {g_Ah, g_Ah, g_Al};
    const __nv_bfloat16* Bbase[3] = {g_Wh, g_Wl, g_Wh};

    float acc[4][8][4];
#pragma unroll
    for (int mi = 0; mi < 4; mi++)
#pragma unroll
        for (int nj = 0; nj < 8; nj++)
#pragma unroll
            for (int q = 0; q < 4; q++) acc[mi][nj][q] = 0.0f;

    // loader: 16B pieces. A: 512 pieces (2/thread). B: 1024 pieces (4/thread).
#define LOAD_TILE(it, buf) do {                                                   \
        const int _t = (it) >> 4;                                                 \
        const int _k0 = ((it) & 15) * BK;                                         \
        const __nv_bfloat16* _Ap = Abase[_t] + (size_t)(by * BM) * D_FEAT + _k0;  \
        const __nv_bfloat16* _Bp = Bbase[_t] + (size_t)(bx * BN) * D_FEAT + _k0;  \
        _Pragma("unroll")                                                         \
        for (int _j = 0; _j < 2; _j++) {                                          \
            const int _p = tid + _j * 256;                                        \
            const int _r = _p >> 2, _c = (_p & 3) * 8;                            \
            cp_async16(aSm + (buf) * ABUF + (uint32_t)(_r * PAD + _c) * 2,        \
                       _Ap + (size_t)_r * D_FEAT + _c);                           \
        }                                                                         \
        _Pragma("unroll")                                                         \
        for (int _j = 0; _j < 4; _j++) {                                          \
            const int _p = tid + _j * 256;                                        \
            const int _r = _p >> 2, _c = (_p & 3) * 8;                            \
            cp_async16(bSm + (buf) * BBUF + (uint32_t)(_r * PAD + _c) * 2,        \
                       _Bp + (size_t)_r * D_FEAT + _c);                           \
        }                                                                         \
        CP_COMMIT();                                                              \
    } while (0)

    LOAD_TILE(0, 0);

    const int lrow = lid & 15;
    const int lcol8 = (lid >> 4) * 8;

#pragma unroll 1
    for (int it = 0; it < N_ITERS; it++) {
        const int b = it & 1;
        if (it + 1 < N_ITERS) {
            LOAD_TILE(it + 1, b ^ 1);
            CP_WAIT(1);
        } else {
            CP_WAIT(0);
        }
        __syncthreads();

#pragma unroll
        for (int ks = 0; ks < BK; ks += 16) {
            uint32_t af[4][4];
#pragma unroll
            for (int mi = 0; mi < 4; mi++) {
                const uint32_t addr = aSm + b * ABUF +
                    (uint32_t)((wr * 64 + mi * 16 + lrow) * PAD + ks + lcol8) * 2;
                LDMATRIX_X4(af[mi][0], af[mi][1], af[mi][2], af[mi][3], addr);
            }
            uint32_t bf[4][4];
#pragma unroll
            for (int nh = 0; nh < 4; nh++) {
                const uint32_t addr = bSm + b * BBUF +
                    (uint32_t)((wc * 64 + nh * 16 + lrow) * PAD + ks + lcol8) * 2;
                LDMATRIX_X4(bf[nh][0], bf[nh][1], bf[nh][2], bf[nh][3], addr);
            }
#pragma unroll
            for (int mi = 0; mi < 4; mi++)
#pragma unroll
                for (int nj = 0; nj < 8; nj++) {
                    const uint32_t b0 = bf[nj >> 1][(nj & 1)];
                    const uint32_t b1 = bf[nj >> 1][(nj & 1) + 2];
                    mma16816(acc[mi][nj], af[mi], b0, b1);
                }
        }
        __syncthreads();
    }

    // epilogue
    const int qrow = lid >> 2;
    const int qcol = (lid & 3) * 2;
#pragma unroll
    for (int mi = 0; mi < 4; mi++) {
        const size_t r0 = (size_t)by * BM + wr * 64 + mi * 16 + qrow;
#pragma unroll
        for (int nj = 0; nj < 8; nj++) {
            const int c0 = bx * BN + wc * 64 + nj * 8 + qcol;
            *(float2*)(g_h + r0 * UNITS + c0) = make_float2(acc[mi][nj][0], acc[mi][nj][1]);
            *(float2*)(g_h + (r0 + 8) * UNITS + c0) = make_float2(acc[mi][nj][2], acc[mi][nj][3]);
        }
    }
}

// ---------------------------------------------------------------------------
// Aggregate: one block per dst row; fused bias + ReLU. 4-way edge unroll.
// ---------------------------------------------------------------------------
__global__ __launch_bounds__(128) void aggregate_kernel(
    const float* __restrict__ bias, float* __restrict__ out)
{
    const int d = blockIdx.x;
    const int c = threadIdx.x;
    const int beg = g_off[d];
    const int end = g_off[d + 1];

    const float4* __restrict__ h4 = (const float4*)g_h;
    float4 acc = make_float4(0.f, 0.f, 0.f, 0.f);

    int e = beg;
    for (; e + 3 < end; e += 4) {
        const int2 sw0 = g_sorted[e];
        const int2 sw1 = g_sorted[e + 1];
        const int2 sw2 = g_sorted[e + 2];
        const int2 sw3 = g_sorted[e + 3];
        const float4 v0 = __ldg(&h4[(size_t)sw0.x * (UNITS / 4) + c]);
        const float4 v1 = __ldg(&h4[(size_t)sw1.x * (UNITS / 4) + c]);
        const float4 v2 = __ldg(&h4[(size_t)sw2.x * (UNITS / 4) + c]);
        const float4 v3 = __ldg(&h4[(size_t)sw3.x * (UNITS / 4) + c]);
        const float w0 = __int_as_float(sw0.y);
        const float w1 = __int_as_float(sw1.y);
        const float w2 = __int_as_float(sw2.y);
        const float w3 = __int_as_float(sw3.y);
        acc.x = fmaf(w0, v0.x, acc.x); acc.y = fmaf(w0, v0.y, acc.y);
        acc.z = fmaf(w0, v0.z, acc.z); acc.w = fmaf(w0, v0.w, acc.w);
        acc.x = fmaf(w1, v1.x, acc.x); acc.y = fmaf(w1, v1.y, acc.y);
        acc.z = fmaf(w1, v1.z, acc.z); acc.w = fmaf(w1, v1.w, acc.w);
        acc.x = fmaf(w2, v2.x, acc.x); acc.y = fmaf(w2, v2.y, acc.y);
        acc.z = fmaf(w2, v2.z, acc.z); acc.w = fmaf(w2, v2.w, acc.w);
        acc.x = fmaf(w3, v3.x, acc.x); acc.y = fmaf(w3, v3.y, acc.y);
        acc.z = fmaf(w3, v3.z, acc.z); acc.w = fmaf(w3, v3.w, acc.w);
    }
    for (; e < end; e++) {
        const int2 sw = g_sorted[e];
        const float4 v = __ldg(&h4[(size_t)sw.x * (UNITS / 4) + c]);
        const float w = __int_as_float(sw.y);
        acc.x = fmaf(w, v.x, acc.x); acc.y = fmaf(w, v.y, acc.y);
        acc.z = fmaf(w, v.z, acc.z); acc.w = fmaf(w, v.w, acc.w);
    }

    const float4 b = ((const float4*)bias)[c];
    float4 r;
    r.x = fmaxf(acc.x + b.x, 0.0f);
    r.y = fmaxf(acc.y + b.y, 0.0f);
    r.z = fmaxf(acc.z + b.z, 0.0f);
    r.w = fmaxf(acc.w + b.w, 0.0f);
    ((float4*)out)[(size_t)d * (UNITS / 4) + c] = r;
}

// ---------------------------------------------------------------------------
extern "C" void kernel_launch(void* const* d_in, const int* in_sizes, int n_in,
                              void* d_out, int out_size)
{
    const float* X    = (const float*)d_in[0];
    const float* W    = (const float*)d_in[1];
    const float* bias = (const float*)d_in[2];
    const float* ew   = (const float*)d_in[3];
    const void*  es   = d_in[4];
    const void*  ed   = d_in[5];
    float* out = (float*)d_out;

    cudaFuncSetAttribute(gemm_mma_kernel,
                         cudaFuncAttributeMaxDynamicSharedMemorySize, GSM);

    // 0) CSR build
    detect_kernel<<<1, 1>>>(es);
    zero_kernel<<<64, 256>>>();
    hist_kernel<<<1024, 256>>>(ed);
    scan_lookback_kernel<<<SCAN_NB, 256>>>();
    place_kernel<<<1024, 256>>>(es, ed, ew);

    // 1) bf16 split prep
    split_X_kernel<<<2048, 256>>>(X);
    split_W_kernel<<<256, 256>>>(W);

    // 2) h = X @ W on tensor cores (bf16 3-term split, fp32 accum)
    dim3 ggrid(UNITS / BN, N_PAD / BM);
    gemm_mma_kernel<<<ggrid, 256, GSM>>>();

    // 3) aggregate + bias + ReLU
    aggregate_kernel<<<N_NODES, 128>>>(bias, out);
}

// round 8
// speedup vs baseline: 4.9129x; 1.1433x over previous
#include <cuda_runtime.h>
#include <cuda_bf16.h>
#include <cuda_fp16.h>
#include <cstdint>

#define N_NODES 50000
#define N_PAD   50048            // 391 * 128
#define N_EDGES 1600000
#define D_FEAT  512
#define UNITS   512

// ---------------- static device scratch (no runtime allocation) ----------
__device__ __half          g_hh[(size_t)N_PAD * UNITS];      // h = X @ W (fp16)
__device__ __nv_bfloat16   g_Ah[(size_t)N_PAD * D_FEAT];     // bf16 split of X
__device__ __nv_bfloat16   g_Al[(size_t)N_PAD * D_FEAT];
__device__ __nv_bfloat16   g_Wh[(size_t)UNITS * D_FEAT];     // W^T split: [n][k]
__device__ __nv_bfloat16   g_Wl[(size_t)UNITS * D_FEAT];
__device__ int   g_deg[N_NODES];
__device__ int   g_cursor[N_NODES];
__device__ int   g_off[N_NODES + 1];
__device__ int2  g_sorted[N_EDGES];
__device__ int   g_is64;

#define SCAN_NB 196               // ceil(50000 / 256)
__device__ int g_blk_flag[SCAN_NB];   // 0=invalid 1=aggregate 2=prefix
__device__ int g_blk_agg[SCAN_NB];
__device__ int g_blk_pref[SCAN_NB];

// ---------------- helpers ------------------------------------------------
__device__ __forceinline__ uint32_t smem_u32(const void* p) {
    uint32_t a;
    asm("{ .reg .u64 t; cvta.to.shared.u64 t, %1; cvt.u32.u64 %0, t; }"
        : "=r"(a) : "l"(p));
    return a;
}
__device__ __forceinline__ void cp_async16(uint32_t dst, const void* src) {
    asm volatile("cp.async.cg.shared.global [%0], [%1], 16;" :: "r"(dst), "l"(src));
}
#define CP_COMMIT() asm volatile("cp.async.commit_group;" ::: "memory")
#define CP_WAIT(n)  asm volatile("cp.async.wait_group %0;" :: "n"(n) : "memory")

#define LDMATRIX_X4(r0, r1, r2, r3, addr) \
    asm volatile("ldmatrix.sync.aligned.m8n8.x4.shared.b16 {%0,%1,%2,%3}, [%4];" \
        : "=r"(r0), "=r"(r1), "=r"(r2), "=r"(r3) : "r"(addr))

__device__ __forceinline__ void mma16816(float* d, const uint32_t* a,
                                         uint32_t b0, uint32_t b1) {
    asm volatile(
        "mma.sync.aligned.m16n8k16.row.col.f32.bf16.bf16.f32 "
        "{%0,%1,%2,%3}, {%4,%5,%6,%7}, {%8,%9}, {%0,%1,%2,%3};"
        : "+f"(d[0]), "+f"(d[1]), "+f"(d[2]), "+f"(d[3])
        : "r"(a[0]), "r"(a[1]), "r"(a[2]), "r"(a[3]), "r"(b0), "r"(b1));
}

// ---------------------------------------------------------------------------
// CSR build
// ---------------------------------------------------------------------------
__global__ void detect_kernel(const void* src_raw)
{
    const long long* p = (const long long*)src_raw;
    int ok64 = 1;
    for (int i = 0; i < 64; i++) {
        long long v = p[i];
        if (v < 0 || v >= N_NODES) { ok64 = 0; break; }
    }
    g_is64 = ok64;
}

__global__ __launch_bounds__(256) void zero_kernel()
{
    const int t = blockIdx.x * blockDim.x + threadIdx.x;
    for (int i = t; i < N_NODES; i += gridDim.x * blockDim.x) {
        g_deg[i] = 0;
        g_cursor[i] = 0;
    }
    if (t < SCAN_NB) g_blk_flag[t] = 0;
    if (t == 0) g_off[N_NODES] = N_EDGES;
}

__global__ __launch_bounds__(256) void hist_kernel(const void* __restrict__ dst_raw)
{
    const int is64 = g_is64;
    for (int i = blockIdx.x * blockDim.x + threadIdx.x;
         i < N_EDGES; i += gridDim.x * blockDim.x) {
        const int d = is64 ? (int)((const long long*)dst_raw)[i]
                           : ((const int*)dst_raw)[i];
        atomicAdd(&g_deg[d], 1);
    }
}

// Decoupled-lookback exclusive scan of g_deg -> g_off. 196 blocks x 256.
__global__ __launch_bounds__(256) void scan_lookback_kernel()
{
    __shared__ int warp_sums[8];
    __shared__ int s_total;
    __shared__ int s_base;

    const int b = blockIdx.x;
    const int tid = threadIdx.x;
    const int i = b * 256 + tid;
    const int lane = tid & 31;
    const int w = tid >> 5;

    const int v = (i < N_NODES) ? g_deg[i] : 0;

    int incl = v;
#pragma unroll
    for (int o = 1; o < 32; o <<= 1) {
        int t = __shfl_up_sync(0xFFFFFFFFu, incl, o);
        if (lane >= o) incl += t;
    }
    if (lane == 31) warp_sums[w] = incl;
    __syncthreads();

    if (w == 0) {
        int ws = (lane < 8) ? warp_sums[lane] : 0;
        int wincl = ws;
#pragma unroll
        for (int o = 1; o < 8; o <<= 1) {
            int t = __shfl_up_sync(0xFFFFFFFFu, wincl, o);
            if (lane >= o) wincl += t;
        }
        if (lane < 8) warp_sums[lane] = wincl - ws;
        if (lane == 7) s_total = wincl;
    }
    __syncthreads();

    if (tid == 0) {
        volatile int* vflag = g_blk_flag;
        volatile int* vagg  = g_blk_agg;
        volatile int* vpref = g_blk_pref;
        g_blk_agg[b] = s_total;
        __threadfence();
        if (b == 0) {
            g_blk_pref[0] = s_total;
            __threadfence();
            vflag[0] = 2;
            s_base = 0;
        } else {
            vflag[b] = 1;
            int running = 0;
            int p = b - 1;
            while (true) {
                int f;
                do { f = vflag[p]; } while (f == 0);
                if (f == 2) { running += vpref[p]; break; }
                running += vagg[p];
                p--;
            }
            s_base = running;
            g_blk_pref[b] = running + s_total;
            __threadfence();
            vflag[b] = 2;
        }
    }
    __syncthreads();

    if (i < N_NODES)
        g_off[i] = s_base + warp_sums[w] + incl - v;
}

__global__ __launch_bounds__(256) void place_kernel(
    const void* __restrict__ src_raw, const void* __restrict__ dst_raw,
    const float* __restrict__ ew)
{
    const int is64 = g_is64;
    for (int i = blockIdx.x * blockDim.x + threadIdx.x;
         i < N_EDGES; i += gridDim.x * blockDim.x) {
        int s, d;
        if (is64) {
            s = (int)((const long long*)src_raw)[i];
            d = (int)((const long long*)dst_raw)[i];
        } else {
            s = ((const int*)src_raw)[i];
            d = ((const int*)dst_raw)[i];
        }
        const int pos = g_off[d] + atomicAdd(&g_cursor[d], 1);
        g_sorted[pos] = make_int2(s, __float_as_int(ew[i]));
    }
}

// ---------------------------------------------------------------------------
// Prep: bf16 split of X (padded rows zeroed) and of W^T.
// ---------------------------------------------------------------------------
__global__ __launch_bounds__(256) void split_X_kernel(const float* __restrict__ X)
{
    const size_t total4 = (size_t)N_PAD * D_FEAT / 4;
    const size_t valid4 = (size_t)N_NODES * D_FEAT / 4;
    for (size_t i = (size_t)blockIdx.x * blockDim.x + threadIdx.x;
         i < total4; i += (size_t)gridDim.x * blockDim.x) {
        float4 x = (i < valid4) ? ((const float4*)X)[i] : make_float4(0.f, 0.f, 0.f, 0.f);
        __nv_bfloat16 h0 = __float2bfloat16(x.x), h1 = __float2bfloat16(x.y);
        __nv_bfloat16 h2 = __float2bfloat16(x.z), h3 = __float2bfloat16(x.w);
        __nv_bfloat16 l0 = __float2bfloat16(x.x - __bfloat162float(h0));
        __nv_bfloat16 l1 = __float2bfloat16(x.y - __bfloat162float(h1));
        __nv_bfloat16 l2 = __float2bfloat16(x.z - __bfloat162float(h2));
        __nv_bfloat16 l3 = __float2bfloat16(x.w - __bfloat162float(h3));
        __nv_bfloat162 hp0 = {h0, h1}, hp1 = {h2, h3};
        __nv_bfloat162 lp0 = {l0, l1}, lp1 = {l2, l3};
        ((uint2*)g_Ah)[i] = make_uint2(*(uint32_t*)&hp0, *(uint32_t*)&hp1);
        ((uint2*)g_Al)[i] = make_uint2(*(uint32_t*)&lp0, *(uint32_t*)&lp1);
    }
}

__global__ __launch_bounds__(256) void split_W_kernel(const float* __restrict__ W)
{
    for (int i = blockIdx.x * blockDim.x + threadIdx.x;
         i < UNITS * D_FEAT; i += gridDim.x * blockDim.x) {
        const int n = i >> 9, k = i & 511;
        const float w = W[(size_t)k * UNITS + n];
        const __nv_bfloat16 h = __float2bfloat16(w);
        const __nv_bfloat16 l = __float2bfloat16(w - __bfloat162float(h));
        g_Wh[i] = h;
        g_Wl[i] = l;
    }
}

// ---------------------------------------------------------------------------
// bf16 mma.sync GEMM: h = Ah*Wh + Ah*Wl + Al*Wh  (fp32 accumulate, fp16 store)
// CTA tile 128x256x32, 8 warps (2x4), warp tile 64x64, double-buffered cp.async.
// ---------------------------------------------------------------------------
#define BM 128
#define BN 256
#define BK 32
#define PAD 40
#define ABUF (BM * PAD * 2)
#define BBUF (BN * PAD * 2)
#define GSM  (2 * (ABUF + BBUF))    // 61440 B dynamic smem
#define N_ITERS 48                  // 3 terms * (512/32)

__global__ __launch_bounds__(256, 1) void gemm_mma_kernel()
{
    extern __shared__ __align__(16) char sm[];
    const uint32_t aSm = smem_u32(sm);
    const uint32_t bSm = aSm + 2 * ABUF;

    const int tid = threadIdx.x;
    const int wid = tid >> 5, lid = tid & 31;
    const int wr = wid >> 2, wc = wid & 3;
    const int bx = blockIdx.x;                 // N tile: 0..1
    const int by = blockIdx.y;                 // M tile: 0..390

    const __nv_bfloat16* Abase[3] = {g_Ah, g_Ah, g_Al};
    const __nv_bfloat16* Bbase[3] = {g_Wh, g_Wl, g_Wh};

    float acc[4][8][4];
#pragma unroll
    for (int mi = 0; mi < 4; mi++)
#pragma unroll
        for (int nj = 0; nj < 8; nj++)
#pragma unroll
            for (int q = 0; q < 4; q++) acc[mi][nj][q] = 0.0f;

#define LOAD_TILE(it, buf) do {                                                   \
        const int _t = (it) >> 4;                                                 \
        const int _k0 = ((it) & 15) * BK;                                         \
        const __nv_bfloat16* _Ap = Abase[_t] + (size_t)(by * BM) * D_FEAT + _k0;  \
        const __nv_bfloat16* _Bp = Bbase[_t] + (size_t)(bx * BN) * D_FEAT + _k0;  \
        _Pragma("unroll")                                                         \
        for (int _j = 0; _j < 2; _j++) {                                          \
            const int _p = tid + _j * 256;                                        \
            const int _r = _p >> 2, _c = (_p & 3) * 8;                            \
            cp_async16(aSm + (buf) * ABUF + (uint32_t)(_r * PAD + _c) * 2,        \
                       _Ap + (size_t)_r * D_FEAT + _c);                           \
        }                                                                         \
        _Pragma("unroll")                                                         \
        for (int _j = 0; _j < 4; _j++) {                                          \
            const int _p = tid + _j * 256;                                        \
            const int _r = _p >> 2, _c = (_p & 3) * 8;                            \
            cp_async16(bSm + (buf) * BBUF + (uint32_t)(_r * PAD + _c) * 2,        \
                       _Bp + (size_t)_r * D_FEAT + _c);                           \
        }                                                                         \
        CP_COMMIT();                                                              \
    } while (0)

    LOAD_TILE(0, 0);

    const int lrow = lid & 15;
    const int lcol8 = (lid >> 4) * 8;

#pragma unroll 1
    for (int it = 0; it < N_ITERS; it++) {
        const int b = it & 1;
        if (it + 1 < N_ITERS) {
            LOAD_TILE(it + 1, b ^ 1);
            CP_WAIT(1);
        } else {
            CP_WAIT(0);
        }
        __syncthreads();

#pragma unroll
        for (int ks = 0; ks < BK; ks += 16) {
            uint32_t af[4][4];
#pragma unroll
            for (int mi = 0; mi < 4; mi++) {
                const uint32_t addr = aSm + b * ABUF +
                    (uint32_t)((wr * 64 + mi * 16 + lrow) * PAD + ks + lcol8) * 2;
                LDMATRIX_X4(af[mi][0], af[mi][1], af[mi][2], af[mi][3], addr);
            }
            uint32_t bf[4][4];
#pragma unroll
            for (int nh = 0; nh < 4; nh++) {
                const uint32_t addr = bSm + b * BBUF +
                    (uint32_t)((wc * 64 + nh * 16 + lrow) * PAD + ks + lcol8) * 2;
                LDMATRIX_X4(bf[nh][0], bf[nh][1], bf[nh][2], bf[nh][3], addr);
            }
#pragma unroll
            for (int mi = 0; mi < 4; mi++)
#pragma unroll
                for (int nj = 0; nj < 8; nj++) {
                    const uint32_t b0 = bf[nj >> 1][(nj & 1)];
                    const uint32_t b1 = bf[nj >> 1][(nj & 1) + 2];
                    mma16816(acc[mi][nj], af[mi], b0, b1);
                }
        }
        __syncthreads();
    }

    // epilogue: fp32 accumulators -> fp16 h
    const int qrow = lid >> 2;
    const int qcol = (lid & 3) * 2;
#pragma unroll
    for (int mi = 0; mi < 4; mi++) {
        const size_t r0 = (size_t)by * BM + wr * 64 + mi * 16 + qrow;
#pragma unroll
        for (int nj = 0; nj < 8; nj++) {
            const int c0 = bx * BN + wc * 64 + nj * 8 + qcol;
            *(__half2*)(g_hh + r0 * UNITS + c0) =
                __float22half2_rn(make_float2(acc[mi][nj][0], acc[mi][nj][1]));
            *(__half2*)(g_hh + (r0 + 8) * UNITS + c0) =
                __float22half2_rn(make_float2(acc[mi][nj][2], acc[mi][nj][3]));
        }
    }
}

// ---------------------------------------------------------------------------
// Aggregate: one block per dst row; fp16 h gather, fp32 accumulate,
// fused bias + ReLU. 4-way edge unroll. Thread c covers 4 cols (uint2 = 4 half).
// ---------------------------------------------------------------------------
__global__ __launch_bounds__(128) void aggregate_kernel(
    const float* __restrict__ bias, float* __restrict__ out)
{
    const int d = blockIdx.x;
    const int c = threadIdx.x;                    // 0..127
    const int beg = g_off[d];
    const int end = g_off[d + 1];

    const uint2* __restrict__ h2 = (const uint2*)g_hh;   // 128 uint2 per row
    float4 acc = make_float4(0.f, 0.f, 0.f, 0.f);

#define ACC_EDGE(sw) do {                                                     \
        const uint2 u = __ldg(&h2[(size_t)(sw).x * (UNITS / 4) + c]);         \
        const float w = __int_as_float((sw).y);                               \
        const float2 f0 = __half22float2(*(const __half2*)&u.x);              \
        const float2 f1 = __half22float2(*(const __half2*)&u.y);              \
        acc.x = fmaf(w, f0.x, acc.x); acc.y = fmaf(w, f0.y, acc.y);           \
        acc.z = fmaf(w, f1.x, acc.z); acc.w = fmaf(w, f1.y, acc.w);           \
    } while (0)

    int e = beg;
    for (; e + 3 < end; e += 4) {
        const int2 sw0 = g_sorted[e];
        const int2 sw1 = g_sorted[e + 1];
        const int2 sw2 = g_sorted[e + 2];
        const int2 sw3 = g_sorted[e + 3];
        ACC_EDGE(sw0);
        ACC_EDGE(sw1);
        ACC_EDGE(sw2);
        ACC_EDGE(sw3);
    }
    for (; e < end; e++) {
        const int2 sw = g_sorted[e];
        ACC_EDGE(sw);
    }

    const float4 b = ((const float4*)bias)[c];
    float4 r;
    r.x = fmaxf(acc.x + b.x, 0.0f);
    r.y = fmaxf(acc.y + b.y, 0.0f);
    r.z = fmaxf(acc.z + b.z, 0.0f);
    r.w = fmaxf(acc.w + b.w, 0.0f);
    ((float4*)out)[(size_t)d * (UNITS / 4) + c] = r;
}

// ---------------------------------------------------------------------------
extern "C" void kernel_launch(void* const* d_in, const int* in_sizes, int n_in,
                              void* d_out, int out_size)
{
    const float* X    = (const float*)d_in[0];
    const float* W    = (const float*)d_in[1];
    const float* bias = (const float*)d_in[2];
    const float* ew   = (const float*)d_in[3];
    const void*  es   = d_in[4];
    const void*  ed   = d_in[5];
    float* out = (float*)d_out;

    cudaFuncSetAttribute(gemm_mma_kernel,
                         cudaFuncAttributeMaxDynamicSharedMemorySize, GSM);

    // 0) CSR build
    detect_kernel<<<1, 1>>>(es);
    zero_kernel<<<64, 256>>>();
    hist_kernel<<<1024, 256>>>(ed);
    scan_lookback_kernel<<<SCAN_NB, 256>>>();
    place_kernel<<<1024, 256>>>(es, ed, ew);

    // 1) bf16 split prep
    split_X_kernel<<<2048, 256>>>(X);
    split_W_kernel<<<256, 256>>>(W);

    // 2) h = X @ W on tensor cores (bf16 3-term split, fp32 accum, fp16 store)
    dim3 ggrid(UNITS / BN, N_PAD / BM);
    gemm_mma_kernel<<<ggrid, 256, GSM>>>();

    // 3) aggregate + bias + ReLU (fp16 gather)
    aggregate_kernel<<<N_NODES, 128>>>(bias, out);
}

// round 9
// speedup vs baseline: 5.2588x; 1.0704x over previous
#include <cuda_runtime.h>
#include <cuda_bf16.h>
#include <cuda_fp16.h>
#include <cstdint>

#define N_NODES 50000
#define N_PAD   50048            // 391 * 128
#define N_EDGES 1600000
#define D_FEAT  512
#define UNITS   512

// ---------------- static device scratch (no runtime allocation) ----------
__device__ __half          g_hh[(size_t)N_PAD * UNITS];      // h = X @ W (fp16)
__device__ __nv_bfloat16   g_Ah[(size_t)N_PAD * D_FEAT];     // bf16 split of X
__device__ __nv_bfloat16   g_Al[(size_t)N_PAD * D_FEAT];
__device__ __nv_bfloat16   g_Wh[(size_t)UNITS * D_FEAT];     // W^T split: [n][k]
__device__ __nv_bfloat16   g_Wl[(size_t)UNITS * D_FEAT];
__device__ int   g_deg[N_NODES];
__device__ int   g_cursor[N_NODES];
__device__ int   g_off[N_NODES + 1];
__device__ int2  g_sorted[N_EDGES];
__device__ int   g_is64;

#define SCAN_NB 196               // ceil(50000 / 256)
__device__ int g_blk_flag[SCAN_NB];   // 0=invalid 1=aggregate 2=prefix
__device__ int g_blk_agg[SCAN_NB];
__device__ int g_blk_pref[SCAN_NB];

// ---------------- helpers ------------------------------------------------
__device__ __forceinline__ uint32_t smem_u32(const void* p) {
    uint32_t a;
    asm("{ .reg .u64 t; cvta.to.shared.u64 t, %1; cvt.u32.u64 %0, t; }"
        : "=r"(a) : "l"(p));
    return a;
}
__device__ __forceinline__ void cp_async16(uint32_t dst, const void* src) {
    asm volatile("cp.async.cg.shared.global [%0], [%1], 16;" :: "r"(dst), "l"(src));
}
#define CP_COMMIT() asm volatile("cp.async.commit_group;" ::: "memory")
#define CP_WAIT(n)  asm volatile("cp.async.wait_group %0;" :: "n"(n) : "memory")

#define LDMATRIX_X4(r0, r1, r2, r3, addr) \
    asm volatile("ldmatrix.sync.aligned.m8n8.x4.shared.b16 {%0,%1,%2,%3}, [%4];" \
        : "=r"(r0), "=r"(r1), "=r"(r2), "=r"(r3) : "r"(addr))

__device__ __forceinline__ void mma16816(float* d, const uint32_t* a,
                                         uint32_t b0, uint32_t b1) {
    asm volatile(
        "mma.sync.aligned.m16n8k16.row.col.f32.bf16.bf16.f32 "
        "{%0,%1,%2,%3}, {%4,%5,%6,%7}, {%8,%9}, {%0,%1,%2,%3};"
        : "+f"(d[0]), "+f"(d[1]), "+f"(d[2]), "+f"(d[3])
        : "r"(a[0]), "r"(a[1]), "r"(a[2]), "r"(a[3]), "r"(b0), "r"(b1));
}

// ---------------------------------------------------------------------------
// CSR build
// ---------------------------------------------------------------------------
__global__ void detect_kernel(const void* src_raw)
{
    const long long* p = (const long long*)src_raw;
    int ok64 = 1;
    for (int i = 0; i < 64; i++) {
        long long v = p[i];
        if (v < 0 || v >= N_NODES) { ok64 = 0; break; }
    }
    g_is64 = ok64;
}

__global__ __launch_bounds__(256) void zero_kernel()
{
    const int t = blockIdx.x * blockDim.x + threadIdx.x;
    for (int i = t; i < N_NODES; i += gridDim.x * blockDim.x) {
        g_deg[i] = 0;
        g_cursor[i] = 0;
    }
    if (t < SCAN_NB) g_blk_flag[t] = 0;
    if (t == 0) g_off[N_NODES] = N_EDGES;
}

__global__ __launch_bounds__(256) void hist_kernel(const void* __restrict__ dst_raw)
{
    const int is64 = g_is64;
    for (int i = blockIdx.x * blockDim.x + threadIdx.x;
         i < N_EDGES; i += gridDim.x * blockDim.x) {
        const int d = is64 ? (int)((const long long*)dst_raw)[i]
                           : ((const int*)dst_raw)[i];
        atomicAdd(&g_deg[d], 1);
    }
}

// Decoupled-lookback exclusive scan of g_deg -> g_off. 196 blocks x 256.
__global__ __launch_bounds__(256) void scan_lookback_kernel()
{
    __shared__ int warp_sums[8];
    __shared__ int s_total;
    __shared__ int s_base;

    const int b = blockIdx.x;
    const int tid = threadIdx.x;
    const int i = b * 256 + tid;
    const int lane = tid & 31;
    const int w = tid >> 5;

    const int v = (i < N_NODES) ? g_deg[i] : 0;

    int incl = v;
#pragma unroll
    for (int o = 1; o < 32; o <<= 1) {
        int t = __shfl_up_sync(0xFFFFFFFFu, incl, o);
        if (lane >= o) incl += t;
    }
    if (lane == 31) warp_sums[w] = incl;
    __syncthreads();

    if (w == 0) {
        int ws = (lane < 8) ? warp_sums[lane] : 0;
        int wincl = ws;
#pragma unroll
        for (int o = 1; o < 8; o <<= 1) {
            int t = __shfl_up_sync(0xFFFFFFFFu, wincl, o);
            if (lane >= o) wincl += t;
        }
        if (lane < 8) warp_sums[lane] = wincl - ws;
        if (lane == 7) s_total = wincl;
    }
    __syncthreads();

    if (tid == 0) {
        volatile int* vflag = g_blk_flag;
        volatile int* vagg  = g_blk_agg;
        volatile int* vpref = g_blk_pref;
        g_blk_agg[b] = s_total;
        __threadfence();
        if (b == 0) {
            g_blk_pref[0] = s_total;
            __threadfence();
            vflag[0] = 2;
            s_base = 0;
        } else {
            vflag[b] = 1;
            int running = 0;
            int p = b - 1;
            while (true) {
                int f;
                do { f = vflag[p]; } while (f == 0);
                if (f == 2) { running += vpref[p]; break; }
                running += vagg[p];
                p--;
            }
            s_base = running;
            g_blk_pref[b] = running + s_total;
            __threadfence();
            vflag[b] = 2;
        }
    }
    __syncthreads();

    if (i < N_NODES)
        g_off[i] = s_base + warp_sums[w] + incl - v;
}

__global__ __launch_bounds__(256) void place_kernel(
    const void* __restrict__ src_raw, const void* __restrict__ dst_raw,
    const float* __restrict__ ew)
{
    const int is64 = g_is64;
    for (int i = blockIdx.x * blockDim.x + threadIdx.x;
         i < N_EDGES; i += gridDim.x * blockDim.x) {
        int s, d;
        if (is64) {
            s = (int)((const long long*)src_raw)[i];
            d = (int)((const long long*)dst_raw)[i];
        } else {
            s = ((const int*)src_raw)[i];
            d = ((const int*)dst_raw)[i];
        }
        const int pos = g_off[d] + atomicAdd(&g_cursor[d], 1);
        g_sorted[pos] = make_int2(s, __float_as_int(ew[i]));
    }
}

// ---------------------------------------------------------------------------
// Prep: bf16 split of X (padded rows zeroed) and of W^T.
// ---------------------------------------------------------------------------
__global__ __launch_bounds__(256) void split_X_kernel(const float* __restrict__ X)
{
    const size_t total4 = (size_t)N_PAD * D_FEAT / 4;
    const size_t valid4 = (size_t)N_NODES * D_FEAT / 4;
    for (size_t i = (size_t)blockIdx.x * blockDim.x + threadIdx.x;
         i < total4; i += (size_t)gridDim.x * blockDim.x) {
        float4 x = (i < valid4) ? ((const float4*)X)[i] : make_float4(0.f, 0.f, 0.f, 0.f);
        __nv_bfloat16 h0 = __float2bfloat16(x.x), h1 = __float2bfloat16(x.y);
        __nv_bfloat16 h2 = __float2bfloat16(x.z), h3 = __float2bfloat16(x.w);
        __nv_bfloat16 l0 = __float2bfloat16(x.x - __bfloat162float(h0));
        __nv_bfloat16 l1 = __float2bfloat16(x.y - __bfloat162float(h1));
        __nv_bfloat16 l2 = __float2bfloat16(x.z - __bfloat162float(h2));
        __nv_bfloat16 l3 = __float2bfloat16(x.w - __bfloat162float(h3));
        __nv_bfloat162 hp0 = {h0, h1}, hp1 = {h2, h3};
        __nv_bfloat162 lp0 = {l0, l1}, lp1 = {l2, l3};
        ((uint2*)g_Ah)[i] = make_uint2(*(uint32_t*)&hp0, *(uint32_t*)&hp1);
        ((uint2*)g_Al)[i] = make_uint2(*(uint32_t*)&lp0, *(uint32_t*)&lp1);
    }
}

__global__ __launch_bounds__(256) void split_W_kernel(const float* __restrict__ W)
{
    for (int i = blockIdx.x * blockDim.x + threadIdx.x;
         i < UNITS * D_FEAT; i += gridDim.x * blockDim.x) {
        const int n = i >> 9, k = i & 511;
        const float w = W[(size_t)k * UNITS + n];
        const __nv_bfloat16 h = __float2bfloat16(w);
        const __nv_bfloat16 l = __float2bfloat16(w - __bfloat162float(h));
        g_Wh[i] = h;
        g_Wl[i] = l;
    }
}

// ---------------------------------------------------------------------------
// bf16 mma.sync GEMM: h = Ah*Wh + Ah*Wl + Al*Wh  (fp32 accumulate, fp16 store)
// CTA tile 128x256x32, 8 warps (2x4), warp tile 64x64, double-buffered cp.async.
// ---------------------------------------------------------------------------
#define BM 128
#define BN 256
#define BK 32
#define PAD 40
#define ABUF (BM * PAD * 2)
#define BBUF (BN * PAD * 2)
#define GSM  (2 * (ABUF + BBUF))    // 61440 B dynamic smem
#define N_ITERS 48                  // 3 terms * (512/32)

__global__ __launch_bounds__(256, 1) void gemm_mma_kernel()
{
    extern __shared__ __align__(16) char sm[];
    const uint32_t aSm = smem_u32(sm);
    const uint32_t bSm = aSm + 2 * ABUF;

    const int tid = threadIdx.x;
    const int wid = tid >> 5, lid = tid & 31;
    const int wr = wid >> 2, wc = wid & 3;
    const int bx = blockIdx.x;                 // N tile: 0..1
    const int by = blockIdx.y;                 // M tile: 0..390

    const __nv_bfloat16* Abase[3] = {g_Ah, g_Ah, g_Al};
    const __nv_bfloat16* Bbase[3] = {g_Wh, g_Wl, g_Wh};

    float acc[4][8][4];
#pragma unroll
    for (int mi = 0; mi < 4; mi++)
#pragma unroll
        for (int nj = 0; nj < 8; nj++)
#pragma unroll
            for (int q = 0; q < 4; q++) acc[mi][nj][q] = 0.0f;

#define LOAD_TILE(it, buf) do {                                                   \
        const int _t = (it) >> 4;                                                 \
        const int _k0 = ((it) & 15) * BK;                                         \
        const __nv_bfloat16* _Ap = Abase[_t] + (size_t)(by * BM) * D_FEAT + _k0;  \
        const __nv_bfloat16* _Bp = Bbase[_t] + (size_t)(bx * BN) * D_FEAT + _k0;  \
        _Pragma("unroll")                                                         \
        for (int _j = 0; _j < 2; _j++) {                                          \
            const int _p = tid + _j * 256;                                        \
            const int _r = _p >> 2, _c = (_p & 3) * 8;                            \
            cp_async16(aSm + (buf) * ABUF + (uint32_t)(_r * PAD + _c) * 2,        \
                       _Ap + (size_t)_r * D_FEAT + _c);                           \
        }                                                                         \
        _Pragma("unroll")                                                         \
        for (int _j = 0; _j < 4; _j++) {                                          \
            const int _p = tid + _j * 256;                                        \
            const int _r = _p >> 2, _c = (_p & 3) * 8;                            \
            cp_async16(bSm + (buf) * BBUF + (uint32_t)(_r * PAD + _c) * 2,        \
                       _Bp + (size_t)_r * D_FEAT + _c);                           \
        }                                                                         \
        CP_COMMIT();                                                              \
    } while (0)

    LOAD_TILE(0, 0);

    const int lrow = lid & 15;
    const int lcol8 = (lid >> 4) * 8;

#pragma unroll 1
    for (int it = 0; it < N_ITERS; it++) {
        const int b = it & 1;
        if (it + 1 < N_ITERS) {
            LOAD_TILE(it + 1, b ^ 1);
            CP_WAIT(1);
        } else {
            CP_WAIT(0);
        }
        __syncthreads();

#pragma unroll
        for (int ks = 0; ks < BK; ks += 16) {
            uint32_t af[4][4];
#pragma unroll
            for (int mi = 0; mi < 4; mi++) {
                const uint32_t addr = aSm + b * ABUF +
                    (uint32_t)((wr * 64 + mi * 16 + lrow) * PAD + ks + lcol8) * 2;
                LDMATRIX_X4(af[mi][0], af[mi][1], af[mi][2], af[mi][3], addr);
            }
            uint32_t bf[4][4];
#pragma unroll
            for (int nh = 0; nh < 4; nh++) {
                const uint32_t addr = bSm + b * BBUF +
                    (uint32_t)((wc * 64 + nh * 16 + lrow) * PAD + ks + lcol8) * 2;
                LDMATRIX_X4(bf[nh][0], bf[nh][1], bf[nh][2], bf[nh][3], addr);
            }
#pragma unroll
            for (int mi = 0; mi < 4; mi++)
#pragma unroll
                for (int nj = 0; nj < 8; nj++) {
                    const uint32_t b0 = bf[nj >> 1][(nj & 1)];
                    const uint32_t b1 = bf[nj >> 1][(nj & 1) + 2];
                    mma16816(acc[mi][nj], af[mi], b0, b1);
                }
        }
        __syncthreads();
    }

    // epilogue: fp32 accumulators -> fp16 h
    const int qrow = lid >> 2;
    const int qcol = (lid & 3) * 2;
#pragma unroll
    for (int mi = 0; mi < 4; mi++) {
        const size_t r0 = (size_t)by * BM + wr * 64 + mi * 16 + qrow;
#pragma unroll
        for (int nj = 0; nj < 8; nj++) {
            const int c0 = bx * BN + wc * 64 + nj * 8 + qcol;
            *(__half2*)(g_hh + r0 * UNITS + c0) =
                __float22half2_rn(make_float2(acc[mi][nj][0], acc[mi][nj][1]));
            *(__half2*)(g_hh + (r0 + 8) * UNITS + c0) =
                __float22half2_rn(make_float2(acc[mi][nj][2], acc[mi][nj][3]));
        }
    }
}

// ---------------------------------------------------------------------------
// Aggregate: one block per dst row; fp16 h gather, fp32 accumulate,
// fused bias + ReLU. 4-way edge unroll.
// ---------------------------------------------------------------------------
__global__ __launch_bounds__(128) void aggregate_kernel(
    const float* __restrict__ bias, float* __restrict__ out)
{
    const int d = blockIdx.x;
    const int c = threadIdx.x;                    // 0..127
    const int beg = g_off[d];
    const int end = g_off[d + 1];

    const uint2* __restrict__ h2 = (const uint2*)g_hh;   // 128 uint2 per row
    float4 acc = make_float4(0.f, 0.f, 0.f, 0.f);

#define ACC_EDGE(sw) do {                                                     \
        const uint2 u = __ldg(&h2[(size_t)(sw).x * (UNITS / 4) + c]);         \
        const float w = __int_as_float((sw).y);                               \
        const float2 f0 = __half22float2(*(const __half2*)&u.x);              \
        const float2 f1 = __half22float2(*(const __half2*)&u.y);              \
        acc.x = fmaf(w, f0.x, acc.x); acc.y = fmaf(w, f0.y, acc.y);           \
        acc.z = fmaf(w, f1.x, acc.z); acc.w = fmaf(w, f1.y, acc.w);           \
    } while (0)

    int e = beg;
    for (; e + 3 < end; e += 4) {
        const int2 sw0 = g_sorted[e];
        const int2 sw1 = g_sorted[e + 1];
        const int2 sw2 = g_sorted[e + 2];
        const int2 sw3 = g_sorted[e + 3];
        ACC_EDGE(sw0);
        ACC_EDGE(sw1);
        ACC_EDGE(sw2);
        ACC_EDGE(sw3);
    }
    for (; e < end; e++) {
        const int2 sw = g_sorted[e];
        ACC_EDGE(sw);
    }

    const float4 b = ((const float4*)bias)[c];
    float4 r;
    r.x = fmaxf(acc.x + b.x, 0.0f);
    r.y = fmaxf(acc.y + b.y, 0.0f);
    r.z = fmaxf(acc.z + b.z, 0.0f);
    r.w = fmaxf(acc.w + b.w, 0.0f);
    ((float4*)out)[(size_t)d * (UNITS / 4) + c] = r;
}

// ---------------------------------------------------------------------------
extern "C" void kernel_launch(void* const* d_in, const int* in_sizes, int n_in,
                              void* d_out, int out_size)
{
    const float* X    = (const float*)d_in[0];
    const float* W    = (const float*)d_in[1];
    const float* bias = (const float*)d_in[2];
    const float* ew   = (const float*)d_in[3];
    const void*  es   = d_in[4];
    const void*  ed   = d_in[5];
    float* out = (float*)d_out;

    // One-time host-side setup (runs on the pre-capture correctness call;
    // no device memory is allocated).
    static cudaStream_t s_csr = nullptr;
    static cudaEvent_t evFork = nullptr, evJoin = nullptr;
    if (!s_csr) {
        cudaStreamCreateWithFlags(&s_csr, cudaStreamNonBlocking);
        cudaEventCreateWithFlags(&evFork, cudaEventDisableTiming);
        cudaEventCreateWithFlags(&evJoin, cudaEventDisableTiming);
        cudaFuncSetAttribute(gemm_mma_kernel,
                             cudaFuncAttributeMaxDynamicSharedMemorySize, GSM);
    }

    // ---- fork: CSR build branch on s_csr, split+GEMM on main stream ----
    cudaEventRecord(evFork, 0);
    cudaStreamWaitEvent(s_csr, evFork, 0);

    // branch A (s_csr): CSR build
    detect_kernel<<<1, 1, 0, s_csr>>>(es);
    zero_kernel<<<64, 256, 0, s_csr>>>();
    hist_kernel<<<1024, 256, 0, s_csr>>>(ed);
    scan_lookback_kernel<<<SCAN_NB, 256, 0, s_csr>>>();
    place_kernel<<<1024, 256, 0, s_csr>>>(es, ed, ew);
    cudaEventRecord(evJoin, s_csr);

    // branch B (main): bf16 split prep + tensor-core GEMM
    split_X_kernel<<<2048, 256>>>(X);
    split_W_kernel<<<256, 256>>>(W);
    dim3 ggrid(UNITS / BN, N_PAD / BM);
    gemm_mma_kernel<<<ggrid, 256, GSM>>>();

    // ---- join, then aggregate (needs both g_hh and CSR) ----
    cudaStreamWaitEvent(0, evJoin, 0);
    aggregate_kernel<<<N_NODES, 128>>>(bias, out);
}

// round 10
// speedup vs baseline: 8.9476x; 1.7015x over previous
#include <cuda_runtime.h>
#include <cuda_bf16.h>
#include <cuda_fp16.h>
#include <cstdint>

#define N_NODES 50000
#define N_PAD   50048            // 391 * 128
#define N_EDGES 1600000
#define D_FEAT  512
#define UNITS   512

// ---------------- static device scratch (no runtime allocation) ----------
__device__ __half g_hh[(size_t)N_PAD * UNITS];      // h = X @ W (fp16)
__device__ __half g_Xh[(size_t)N_PAD * D_FEAT];     // X in fp16
__device__ __half g_Wt[(size_t)UNITS * D_FEAT];     // W^T in fp16: [n][k]
__device__ int   g_deg[N_NODES];
__device__ int   g_cursor[N_NODES];
__device__ int   g_off[N_NODES + 1];
__device__ int2  g_sorted[N_EDGES];
__device__ int   g_is64;

#define SCAN_NB 196               // ceil(50000 / 256)
__device__ int g_blk_flag[SCAN_NB];   // 0=invalid 1=aggregate 2=prefix
__device__ int g_blk_agg[SCAN_NB];
__device__ int g_blk_pref[SCAN_NB];

// ---------------- helpers ------------------------------------------------
__device__ __forceinline__ uint32_t smem_u32(const void* p) {
    uint32_t a;
    asm("{ .reg .u64 t; cvta.to.shared.u64 t, %1; cvt.u32.u64 %0, t; }"
        : "=r"(a) : "l"(p));
    return a;
}
__device__ __forceinline__ void cp_async16(uint32_t dst, const void* src) {
    asm volatile("cp.async.cg.shared.global [%0], [%1], 16;" :: "r"(dst), "l"(src));
}
#define CP_COMMIT() asm volatile("cp.async.commit_group;" ::: "memory")
#define CP_WAIT(n)  asm volatile("cp.async.wait_group %0;" :: "n"(n) : "memory")

#define LDMATRIX_X4(r0, r1, r2, r3, addr) \
    asm volatile("ldmatrix.sync.aligned.m8n8.x4.shared.b16 {%0,%1,%2,%3}, [%4];" \
        : "=r"(r0), "=r"(r1), "=r"(r2), "=r"(r3) : "r"(addr))

__device__ __forceinline__ void mma16816_f16(float* d, const uint32_t* a,
                                             uint32_t b0, uint32_t b1) {
    asm volatile(
        "mma.sync.aligned.m16n8k16.row.col.f32.f16.f16.f32 "
        "{%0,%1,%2,%3}, {%4,%5,%6,%7}, {%8,%9}, {%0,%1,%2,%3};"
        : "+f"(d[0]), "+f"(d[1]), "+f"(d[2]), "+f"(d[3])
        : "r"(a[0]), "r"(a[1]), "r"(a[2]), "r"(a[3]), "r"(b0), "r"(b1));
}

// ---------------------------------------------------------------------------
// CSR build
// ---------------------------------------------------------------------------
__global__ void detect_kernel(const void* src_raw)
{
    const long long* p = (const long long*)src_raw;
    int ok64 = 1;
    for (int i = 0; i < 64; i++) {
        long long v = p[i];
        if (v < 0 || v >= N_NODES) { ok64 = 0; break; }
    }
    g_is64 = ok64;
}

__global__ __launch_bounds__(256) void zero_kernel()
{
    const int t = blockIdx.x * blockDim.x + threadIdx.x;
    for (int i = t; i < N_NODES; i += gridDim.x * blockDim.x) {
        g_deg[i] = 0;
        g_cursor[i] = 0;
    }
    if (t < SCAN_NB) g_blk_flag[t] = 0;
    if (t == 0) g_off[N_NODES] = N_EDGES;
}

__global__ __launch_bounds__(256) void hist_kernel(const void* __restrict__ dst_raw)
{
    const int is64 = g_is64;
    for (int i = blockIdx.x * blockDim.x + threadIdx.x;
         i < N_EDGES; i += gridDim.x * blockDim.x) {
        const int d = is64 ? (int)((const long long*)dst_raw)[i]
                           : ((const int*)dst_raw)[i];
        atomicAdd(&g_deg[d], 1);
    }
}

// Decoupled-lookback exclusive scan of g_deg -> g_off. 196 blocks x 256.
__global__ __launch_bounds__(256) void scan_lookback_kernel()
{
    __shared__ int warp_sums[8];
    __shared__ int s_total;
    __shared__ int s_base;

    const int b = blockIdx.x;
    const int tid = threadIdx.x;
    const int i = b * 256 + tid;
    const int lane = tid & 31;
    const int w = tid >> 5;

    const int v = (i < N_NODES) ? g_deg[i] : 0;

    int incl = v;
#pragma unroll
    for (int o = 1; o < 32; o <<= 1) {
        int t = __shfl_up_sync(0xFFFFFFFFu, incl, o);
        if (lane >= o) incl += t;
    }
    if (lane == 31) warp_sums[w] = incl;
    __syncthreads();

    if (w == 0) {
        int ws = (lane < 8) ? warp_sums[lane] : 0;
        int wincl = ws;
#pragma unroll
        for (int o = 1; o < 8; o <<= 1) {
            int t = __shfl_up_sync(0xFFFFFFFFu, wincl, o);
            if (lane >= o) wincl += t;
        }
        if (lane < 8) warp_sums[lane] = wincl - ws;
        if (lane == 7) s_total = wincl;
    }
    __syncthreads();

    if (tid == 0) {
        volatile int* vflag = g_blk_flag;
        volatile int* vagg  = g_blk_agg;
        volatile int* vpref = g_blk_pref;
        g_blk_agg[b] = s_total;
        __threadfence();
        if (b == 0) {
            g_blk_pref[0] = s_total;
            __threadfence();
            vflag[0] = 2;
            s_base = 0;
        } else {
            vflag[b] = 1;
            int running = 0;
            int p = b - 1;
            while (true) {
                int f;
                do { f = vflag[p]; } while (f == 0);
                if (f == 2) { running += vpref[p]; break; }
                running += vagg[p];
                p--;
            }
            s_base = running;
            g_blk_pref[b] = running + s_total;
            __threadfence();
            vflag[b] = 2;
        }
    }
    __syncthreads();

    if (i < N_NODES)
        g_off[i] = s_base + warp_sums[w] + incl - v;
}

__global__ __launch_bounds__(256) void place_kernel(
    const void* __restrict__ src_raw, const void* __restrict__ dst_raw,
    const float* __restrict__ ew)
{
    const int is64 = g_is64;
    for (int i = blockIdx.x * blockDim.x + threadIdx.x;
         i < N_EDGES; i += gridDim.x * blockDim.x) {
        int s, d;
        if (is64) {
            s = (int)((const long long*)src_raw)[i];
            d = (int)((const long long*)dst_raw)[i];
        } else {
            s = ((const int*)src_raw)[i];
            d = ((const int*)dst_raw)[i];
        }
        const int pos = g_off[d] + atomicAdd(&g_cursor[d], 1);
        g_sorted[pos] = make_int2(s, __float_as_int(ew[i]));
    }
}

// ---------------------------------------------------------------------------
// Prep: fp16 conversion of X (padded rows zeroed) and W^T.
// ---------------------------------------------------------------------------
__global__ __launch_bounds__(256) void conv_X_kernel(const float* __restrict__ X)
{
    const size_t total4 = (size_t)N_PAD * D_FEAT / 4;
    const size_t valid4 = (size_t)N_NODES * D_FEAT / 4;
    for (size_t i = (size_t)blockIdx.x * blockDim.x + threadIdx.x;
         i < total4; i += (size_t)gridDim.x * blockDim.x) {
        float4 x = (i < valid4) ? ((const float4*)X)[i] : make_float4(0.f, 0.f, 0.f, 0.f);
        __half2 h0 = __float22half2_rn(make_float2(x.x, x.y));
        __half2 h1 = __float22half2_rn(make_float2(x.z, x.w));
        ((uint2*)g_Xh)[i] = make_uint2(*(uint32_t*)&h0, *(uint32_t*)&h1);
    }
}

__global__ __launch_bounds__(256) void conv_W_kernel(const float* __restrict__ W)
{
    for (int i = blockIdx.x * blockDim.x + threadIdx.x;
         i < UNITS * D_FEAT; i += gridDim.x * blockDim.x) {
        const int n = i >> 9, k = i & 511;
        g_Wt[i] = __float2half_rn(W[(size_t)k * UNITS + n]);
    }
}

// ---------------------------------------------------------------------------
// fp16 mma.sync GEMM: h = Xh @ Wt^T  (fp32 accumulate, fp16 store)
// CTA tile 128x256x32, 8 warps (2x4), warp tile 64x64, double-buffered cp.async.
// ---------------------------------------------------------------------------
#define BM 128
#define BN 256
#define BK 32
#define PAD 40
#define ABUF (BM * PAD * 2)
#define BBUF (BN * PAD * 2)
#define GSM  (2 * (ABUF + BBUF))    // 61440 B dynamic smem
#define N_ITERS 16                  // 512 / 32

__global__ __launch_bounds__(256, 1) void gemm_mma_kernel()
{
    extern __shared__ __align__(16) char sm[];
    const uint32_t aSm = smem_u32(sm);
    const uint32_t bSm = aSm + 2 * ABUF;

    const int tid = threadIdx.x;
    const int wid = tid >> 5, lid = tid & 31;
    const int wr = wid >> 2, wc = wid & 3;
    const int bx = blockIdx.x;                 // N tile: 0..1
    const int by = blockIdx.y;                 // M tile: 0..390

    float acc[4][8][4];
#pragma unroll
    for (int mi = 0; mi < 4; mi++)
#pragma unroll
        for (int nj = 0; nj < 8; nj++)
#pragma unroll
            for (int q = 0; q < 4; q++) acc[mi][nj][q] = 0.0f;

#define LOAD_TILE(it, buf) do {                                                   \
        const int _k0 = (it) * BK;                                                \
        const __half* _Ap = g_Xh + (size_t)(by * BM) * D_FEAT + _k0;              \
        const __half* _Bp = g_Wt + (size_t)(bx * BN) * D_FEAT + _k0;              \
        _Pragma("unroll")                                                         \
        for (int _j = 0; _j < 2; _j++) {                                          \
            const int _p = tid + _j * 256;                                        \
            const int _r = _p >> 2, _c = (_p & 3) * 8;                            \
            cp_async16(aSm + (buf) * ABUF + (uint32_t)(_r * PAD + _c) * 2,        \
                       _Ap + (size_t)_r * D_FEAT + _c);                           \
        }                                                                         \
        _Pragma("unroll")                                                         \
        for (int _j = 0; _j < 4; _j++) {                                          \
            const int _p = tid + _j * 256;                                        \
            const int _r = _p >> 2, _c = (_p & 3) * 8;                            \
            cp_async16(bSm + (buf) * BBUF + (uint32_t)(_r * PAD + _c) * 2,        \
                       _Bp + (size_t)_r * D_FEAT + _c);                           \
        }                                                                         \
        CP_COMMIT();                                                              \
    } while (0)

    LOAD_TILE(0, 0);

    const int lrow = lid & 15;
    const int lcol8 = (lid >> 4) * 8;

#pragma unroll 1
    for (int it = 0; it < N_ITERS; it++) {
        const int b = it & 1;
        if (it + 1 < N_ITERS) {
            LOAD_TILE(it + 1, b ^ 1);
            CP_WAIT(1);
        } else {
            CP_WAIT(0);
        }
        __syncthreads();

#pragma unroll
        for (int ks = 0; ks < BK; ks += 16) {
            uint32_t af[4][4];
#pragma unroll
            for (int mi = 0; mi < 4; mi++) {
                const uint32_t addr = aSm + b * ABUF +
                    (uint32_t)((wr * 64 + mi * 16 + lrow) * PAD + ks + lcol8) * 2;
                LDMATRIX_X4(af[mi][0], af[mi][1], af[mi][2], af[mi][3], addr);
            }
            uint32_t bf[4][4];
#pragma unroll
            for (int nh = 0; nh < 4; nh++) {
                const uint32_t addr = bSm + b * BBUF +
                    (uint32_t)((wc * 64 + nh * 16 + lrow) * PAD + ks + lcol8) * 2;
                LDMATRIX_X4(bf[nh][0], bf[nh][1], bf[nh][2], bf[nh][3], addr);
            }
#pragma unroll
            for (int mi = 0; mi < 4; mi++)
#pragma unroll
                for (int nj = 0; nj < 8; nj++) {
                    const uint32_t b0 = bf[nj >> 1][(nj & 1)];
                    const uint32_t b1 = bf[nj >> 1][(nj & 1) + 2];
                    mma16816_f16(acc[mi][nj], af[mi], b0, b1);
                }
        }
        __syncthreads();
    }

    // epilogue: fp32 accumulators -> fp16 h
    const int qrow = lid >> 2;
    const int qcol = (lid & 3) * 2;
#pragma unroll
    for (int mi = 0; mi < 4; mi++) {
        const size_t r0 = (size_t)by * BM + wr * 64 + mi * 16 + qrow;
#pragma unroll
        for (int nj = 0; nj < 8; nj++) {
            const int c0 = bx * BN + wc * 64 + nj * 8 + qcol;
            *(__half2*)(g_hh + r0 * UNITS + c0) =
                __float22half2_rn(make_float2(acc[mi][nj][0], acc[mi][nj][1]));
            *(__half2*)(g_hh + (r0 + 8) * UNITS + c0) =
                __float22half2_rn(make_float2(acc[mi][nj][2], acc[mi][nj][3]));
        }
    }
}

// ---------------------------------------------------------------------------
// Aggregate: one block per dst row; fp16 h gather, fp32 accumulate,
// fused bias + ReLU. 4-way edge unroll.
// ---------------------------------------------------------------------------
__global__ __launch_bounds__(128) void aggregate_kernel(
    const float* __restrict__ bias, float* __restrict__ out)
{
    const int d = blockIdx.x;
    const int c = threadIdx.x;                    // 0..127
    const int beg = g_off[d];
    const int end = g_off[d + 1];

    const uint2* __restrict__ h2 = (const uint2*)g_hh;   // 128 uint2 per row
    float4 acc = make_float4(0.f, 0.f, 0.f, 0.f);

#define ACC_EDGE(sw) do {                                                     \
        const uint2 u = __ldg(&h2[(size_t)(sw).x * (UNITS / 4) + c]);         \
        const float w = __int_as_float((sw).y);                               \
        const float2 f0 = __half22float2(*(const __half2*)&u.x);              \
        const float2 f1 = __half22float2(*(const __half2*)&u.y);              \
        acc.x = fmaf(w, f0.x, acc.x); acc.y = fmaf(w, f0.y, acc.y);           \
        acc.z = fmaf(w, f1.x, acc.z); acc.w = fmaf(w, f1.y, acc.w);           \
    } while (0)

    int e = beg;
    for (; e + 3 < end; e += 4) {
        const int2 sw0 = g_sorted[e];
        const int2 sw1 = g_sorted[e + 1];
        const int2 sw2 = g_sorted[e + 2];
        const int2 sw3 = g_sorted[e + 3];
        ACC_EDGE(sw0);
        ACC_EDGE(sw1);
        ACC_EDGE(sw2);
        ACC_EDGE(sw3);
    }
    for (; e < end; e++) {
        const int2 sw = g_sorted[e];
        ACC_EDGE(sw);
    }

    const float4 b = ((const float4*)bias)[c];
    float4 r;
    r.x = fmaxf(acc.x + b.x, 0.0f);
    r.y = fmaxf(acc.y + b.y, 0.0f);
    r.z = fmaxf(acc.z + b.z, 0.0f);
    r.w = fmaxf(acc.w + b.w, 0.0f);
    ((float4*)out)[(size_t)d * (UNITS / 4) + c] = r;
}

// ---------------------------------------------------------------------------
extern "C" void kernel_launch(void* const* d_in, const int* in_sizes, int n_in,
                              void* d_out, int out_size)
{
    const float* X    = (const float*)d_in[0];
    const float* W    = (const float*)d_in[1];
    const float* bias = (const float*)d_in[2];
    const float* ew   = (const float*)d_in[3];
    const void*  es   = d_in[4];
    const void*  ed   = d_in[5];
    float* out = (float*)d_out;

    // One-time host-side setup (pre-capture correctness call; no device alloc).
    static cudaStream_t s_csr = nullptr;
    static cudaEvent_t evFork = nullptr, evJoin = nullptr;
    if (!s_csr) {
        cudaStreamCreateWithFlags(&s_csr, cudaStreamNonBlocking);
        cudaEventCreateWithFlags(&evFork, cudaEventDisableTiming);
        cudaEventCreateWithFlags(&evJoin, cudaEventDisableTiming);
        cudaFuncSetAttribute(gemm_mma_kernel,
                             cudaFuncAttributeMaxDynamicSharedMemorySize, GSM);
    }

    // ---- fork: CSR build branch on s_csr, convert+GEMM on main stream ----
    cudaEventRecord(evFork, 0);
    cudaStreamWaitEvent(s_csr, evFork, 0);

    // branch A (s_csr): CSR build
    detect_kernel<<<1, 1, 0, s_csr>>>(es);
    zero_kernel<<<64, 256, 0, s_csr>>>();
    hist_kernel<<<1024, 256, 0, s_csr>>>(ed);
    scan_lookback_kernel<<<SCAN_NB, 256, 0, s_csr>>>();
    place_kernel<<<1024, 256, 0, s_csr>>>(es, ed, ew);
    cudaEventRecord(evJoin, s_csr);

    // branch B (main): fp16 convert + tensor-core GEMM
    conv_X_kernel<<<2048, 256>>>(X);
    conv_W_kernel<<<256, 256>>>(W);
    dim3 ggrid(UNITS / BN, N_PAD / BM);
    gemm_mma_kernel<<<ggrid, 256, GSM>>>();

    // ---- join, then aggregate (needs both g_hh and CSR) ----
    cudaStreamWaitEvent(0, evJoin, 0);
    aggregate_kernel<<<N_NODES, 128>>>(bias, out);
}

// round 11
// speedup vs baseline: 9.0269x; 1.0089x over previous
#include <cuda_runtime.h>
#include <cuda_bf16.h>
#include <cuda_fp16.h>
#include <cstdint>

#define N_NODES 50000
#define N_PAD   50048            // 391 * 128
#define N_EDGES 1600000
#define D_FEAT  512
#define UNITS   512

// ---------------- static device scratch (no runtime allocation) ----------
__device__ __half g_hh[(size_t)N_PAD * UNITS];      // h = X @ W (fp16)
__device__ __half g_Xh[(size_t)N_PAD * D_FEAT];     // X in fp16
__device__ __half g_Wt[(size_t)UNITS * D_FEAT];     // W^T in fp16: [n][k]
__device__ int   g_deg[N_NODES];
__device__ int   g_cursor[N_NODES];
__device__ int   g_off[N_NODES + 1];
__device__ int2  g_sorted[N_EDGES];
__device__ int   g_is64;

#define SCAN_NB 196               // ceil(50000 / 256)
__device__ int g_blk_flag[SCAN_NB];   // 0=invalid 1=aggregate 2=prefix
__device__ int g_blk_agg[SCAN_NB];
__device__ int g_blk_pref[SCAN_NB];

// ---------------- helpers ------------------------------------------------
__device__ __forceinline__ uint32_t smem_u32(const void* p) {
    uint32_t a;
    asm("{ .reg .u64 t; cvta.to.shared.u64 t, %1; cvt.u32.u64 %0, t; }"
        : "=r"(a) : "l"(p));
    return a;
}
__device__ __forceinline__ void cp_async16(uint32_t dst, const void* src) {
    asm volatile("cp.async.cg.shared.global [%0], [%1], 16;" :: "r"(dst), "l"(src));
}
#define CP_COMMIT() asm volatile("cp.async.commit_group;" ::: "memory")
#define CP_WAIT(n)  asm volatile("cp.async.wait_group %0;" :: "n"(n) : "memory")

#define LDMATRIX_X4(r0, r1, r2, r3, addr) \
    asm volatile("ldmatrix.sync.aligned.m8n8.x4.shared.b16 {%0,%1,%2,%3}, [%4];" \
        : "=r"(r0), "=r"(r1), "=r"(r2), "=r"(r3) : "r"(addr))

__device__ __forceinline__ void mma16816_f16(float* d, const uint32_t* a,
                                             uint32_t b0, uint32_t b1) {
    asm volatile(
        "mma.sync.aligned.m16n8k16.row.col.f32.f16.f16.f32 "
        "{%0,%1,%2,%3}, {%4,%5,%6,%7}, {%8,%9}, {%0,%1,%2,%3};"
        : "+f"(d[0]), "+f"(d[1]), "+f"(d[2]), "+f"(d[3])
        : "r"(a[0]), "r"(a[1]), "r"(a[2]), "r"(a[3]), "r"(b0), "r"(b1));
}

// ---------------------------------------------------------------------------
// CSR build
// ---------------------------------------------------------------------------
__global__ void detect_kernel(const void* src_raw)
{
    const long long* p = (const long long*)src_raw;
    int ok64 = 1;
    for (int i = 0; i < 64; i++) {
        long long v = p[i];
        if (v < 0 || v >= N_NODES) { ok64 = 0; break; }
    }
    g_is64 = ok64;
}

__global__ __launch_bounds__(256) void zero_kernel()
{
    const int t = blockIdx.x * blockDim.x + threadIdx.x;
    for (int i = t; i < N_NODES; i += gridDim.x * blockDim.x) {
        g_deg[i] = 0;
        g_cursor[i] = 0;
    }
    if (t < SCAN_NB) g_blk_flag[t] = 0;
    if (t == 0) g_off[N_NODES] = N_EDGES;
}

__global__ __launch_bounds__(256) void hist_kernel(const void* __restrict__ dst_raw)
{
    const int is64 = g_is64;
    for (int i = blockIdx.x * blockDim.x + threadIdx.x;
         i < N_EDGES; i += gridDim.x * blockDim.x) {
        const int d = is64 ? (int)((const long long*)dst_raw)[i]
                           : ((const int*)dst_raw)[i];
        atomicAdd(&g_deg[d], 1);
    }
}

// Decoupled-lookback exclusive scan of g_deg -> g_off. 196 blocks x 256.
__global__ __launch_bounds__(256) void scan_lookback_kernel()
{
    __shared__ int warp_sums[8];
    __shared__ int s_total;
    __shared__ int s_base;

    const int b = blockIdx.x;
    const int tid = threadIdx.x;
    const int i = b * 256 + tid;
    const int lane = tid & 31;
    const int w = tid >> 5;

    const int v = (i < N_NODES) ? g_deg[i] : 0;

    int incl = v;
#pragma unroll
    for (int o = 1; o < 32; o <<= 1) {
        int t = __shfl_up_sync(0xFFFFFFFFu, incl, o);
        if (lane >= o) incl += t;
    }
    if (lane == 31) warp_sums[w] = incl;
    __syncthreads();

    if (w == 0) {
        int ws = (lane < 8) ? warp_sums[lane] : 0;
        int wincl = ws;
#pragma unroll
        for (int o = 1; o < 8; o <<= 1) {
            int t = __shfl_up_sync(0xFFFFFFFFu, wincl, o);
            if (lane >= o) wincl += t;
        }
        if (lane < 8) warp_sums[lane] = wincl - ws;
        if (lane == 7) s_total = wincl;
    }
    __syncthreads();

    if (tid == 0) {
        volatile int* vflag = g_blk_flag;
        volatile int* vagg  = g_blk_agg;
        volatile int* vpref = g_blk_pref;
        g_blk_agg[b] = s_total;
        __threadfence();
        if (b == 0) {
            g_blk_pref[0] = s_total;
            __threadfence();
            vflag[0] = 2;
            s_base = 0;
        } else {
            vflag[b] = 1;
            int running = 0;
            int p = b - 1;
            while (true) {
                int f;
                do { f = vflag[p]; } while (f == 0);
                if (f == 2) { running += vpref[p]; break; }
                running += vagg[p];
                p--;
            }
            s_base = running;
            g_blk_pref[b] = running + s_total;
            __threadfence();
            vflag[b] = 2;
        }
    }
    __syncthreads();

    if (i < N_NODES)
        g_off[i] = s_base + warp_sums[w] + incl - v;
}

__global__ __launch_bounds__(256) void place_kernel(
    const void* __restrict__ src_raw, const void* __restrict__ dst_raw,
    const float* __restrict__ ew)
{
    const int is64 = g_is64;
    for (int i = blockIdx.x * blockDim.x + threadIdx.x;
         i < N_EDGES; i += gridDim.x * blockDim.x) {
        int s, d;
        if (is64) {
            s = (int)((const long long*)src_raw)[i];
            d = (int)((const long long*)dst_raw)[i];
        } else {
            s = ((const int*)src_raw)[i];
            d = ((const int*)dst_raw)[i];
        }
        const int pos = g_off[d] + atomicAdd(&g_cursor[d], 1);
        g_sorted[pos] = make_int2(s, __float_as_int(ew[i]));
    }
}

// ---------------------------------------------------------------------------
// Prep: fp16 conversion of X (padded rows zeroed) and W^T.
// ---------------------------------------------------------------------------
__global__ __launch_bounds__(256) void conv_X_kernel(const float* __restrict__ X)
{
    const size_t total4 = (size_t)N_PAD * D_FEAT / 4;
    const size_t valid4 = (size_t)N_NODES * D_FEAT / 4;
    for (size_t i = (size_t)blockIdx.x * blockDim.x + threadIdx.x;
         i < total4; i += (size_t)gridDim.x * blockDim.x) {
        float4 x = (i < valid4) ? ((const float4*)X)[i] : make_float4(0.f, 0.f, 0.f, 0.f);
        __half2 h0 = __float22half2_rn(make_float2(x.x, x.y));
        __half2 h1 = __float22half2_rn(make_float2(x.z, x.w));
        ((uint2*)g_Xh)[i] = make_uint2(*(uint32_t*)&h0, *(uint32_t*)&h1);
    }
}

__global__ __launch_bounds__(256) void conv_W_kernel(const float* __restrict__ W)
{
    for (int i = blockIdx.x * blockDim.x + threadIdx.x;
         i < UNITS * D_FEAT; i += gridDim.x * blockDim.x) {
        const int n = i >> 9, k = i & 511;
        g_Wt[i] = __float2half_rn(W[(size_t)k * UNITS + n]);
    }
}

// ---------------------------------------------------------------------------
// fp16 mma.sync GEMM: h = Xh @ Wt^T  (fp32 accumulate, fp16 store)
// CTA tile 128x256x32. Launched per N-column-half (bx passed as param).
// ---------------------------------------------------------------------------
#define BM 128
#define BN 256
#define BK 32
#define PAD 40
#define ABUF (BM * PAD * 2)
#define BBUF (BN * PAD * 2)
#define GSM  (2 * (ABUF + BBUF))    // 61440 B dynamic smem
#define N_ITERS 16                  // 512 / 32

__global__ __launch_bounds__(256, 1) void gemm_mma_kernel(int bx)
{
    extern __shared__ __align__(16) char sm[];
    const uint32_t aSm = smem_u32(sm);
    const uint32_t bSm = aSm + 2 * ABUF;

    const int tid = threadIdx.x;
    const int wid = tid >> 5, lid = tid & 31;
    const int wr = wid >> 2, wc = wid & 3;
    const int by = blockIdx.x;                 // M tile: 0..390

    float acc[4][8][4];
#pragma unroll
    for (int mi = 0; mi < 4; mi++)
#pragma unroll
        for (int nj = 0; nj < 8; nj++)
#pragma unroll
            for (int q = 0; q < 4; q++) acc[mi][nj][q] = 0.0f;

#define LOAD_TILE(it, buf) do {                                                   \
        const int _k0 = (it) * BK;                                                \
        const __half* _Ap = g_Xh + (size_t)(by * BM) * D_FEAT + _k0;              \
        const __half* _Bp = g_Wt + (size_t)(bx * BN) * D_FEAT + _k0;              \
        _Pragma("unroll")                                                         \
        for (int _j = 0; _j < 2; _j++) {                                          \
            const int _p = tid + _j * 256;                                        \
            const int _r = _p >> 2, _c = (_p & 3) * 8;                            \
            cp_async16(aSm + (buf) * ABUF + (uint32_t)(_r * PAD + _c) * 2,        \
                       _Ap + (size_t)_r * D_FEAT + _c);                           \
        }                                                                         \
        _Pragma("unroll")                                                         \
        for (int _j = 0; _j < 4; _j++) {                                          \
            const int _p = tid + _j * 256;                                        \
            const int _r = _p >> 2, _c = (_p & 3) * 8;                            \
            cp_async16(bSm + (buf) * BBUF + (uint32_t)(_r * PAD + _c) * 2,        \
                       _Bp + (size_t)_r * D_FEAT + _c);                           \
        }                                                                         \
        CP_COMMIT();                                                              \
    } while (0)

    LOAD_TILE(0, 0);

    const int lrow = lid & 15;
    const int lcol8 = (lid >> 4) * 8;

#pragma unroll 1
    for (int it = 0; it < N_ITERS; it++) {
        const int b = it & 1;
        if (it + 1 < N_ITERS) {
            LOAD_TILE(it + 1, b ^ 1);
            CP_WAIT(1);
        } else {
            CP_WAIT(0);
        }
        __syncthreads();

#pragma unroll
        for (int ks = 0; ks < BK; ks += 16) {
            uint32_t af[4][4];
#pragma unroll
            for (int mi = 0; mi < 4; mi++) {
                const uint32_t addr = aSm + b * ABUF +
                    (uint32_t)((wr * 64 + mi * 16 + lrow) * PAD + ks + lcol8) * 2;
                LDMATRIX_X4(af[mi][0], af[mi][1], af[mi][2], af[mi][3], addr);
            }
            uint32_t bf[4][4];
#pragma unroll
            for (int nh = 0; nh < 4; nh++) {
                const uint32_t addr = bSm + b * BBUF +
                    (uint32_t)((wc * 64 + nh * 16 + lrow) * PAD + ks + lcol8) * 2;
                LDMATRIX_X4(bf[nh][0], bf[nh][1], bf[nh][2], bf[nh][3], addr);
            }
#pragma unroll
            for (int mi = 0; mi < 4; mi++)
#pragma unroll
                for (int nj = 0; nj < 8; nj++) {
                    const uint32_t b0 = bf[nj >> 1][(nj & 1)];
                    const uint32_t b1 = bf[nj >> 1][(nj & 1) + 2];
                    mma16816_f16(acc[mi][nj], af[mi], b0, b1);
                }
        }
        __syncthreads();
    }

    // epilogue: fp32 accumulators -> fp16 h
    const int qrow = lid >> 2;
    const int qcol = (lid & 3) * 2;
#pragma unroll
    for (int mi = 0; mi < 4; mi++) {
        const size_t r0 = (size_t)by * BM + wr * 64 + mi * 16 + qrow;
#pragma unroll
        for (int nj = 0; nj < 8; nj++) {
            const int c0 = bx * BN + wc * 64 + nj * 8 + qcol;
            *(__half2*)(g_hh + r0 * UNITS + c0) =
                __float22half2_rn(make_float2(acc[mi][nj][0], acc[mi][nj][1]));
            *(__half2*)(g_hh + (r0 + 8) * UNITS + c0) =
                __float22half2_rn(make_float2(acc[mi][nj][2], acc[mi][nj][3]));
        }
    }
}

// ---------------------------------------------------------------------------
// Aggregate over a 256-column half. One block (64 threads) per dst row.
// fp16 gather, fp32 accumulate, fused bias + ReLU. 4-way edge unroll.
// ---------------------------------------------------------------------------
__global__ __launch_bounds__(64) void aggregate_half_kernel(
    const float* __restrict__ bias, float* __restrict__ out, int colbase4)
{
    const int d = blockIdx.x;
    const int c = colbase4 + threadIdx.x;         // uint2 index within row (0..127)
    const int beg = g_off[d];
    const int end = g_off[d + 1];

    const uint2* __restrict__ h2 = (const uint2*)g_hh;   // 128 uint2 per row
    float4 acc = make_float4(0.f, 0.f, 0.f, 0.f);

#define ACC_EDGE(sw) do {                                                     \
        const uint2 u = __ldg(&h2[(size_t)(sw).x * (UNITS / 4) + c]);         \
        const float w = __int_as_float((sw).y);                               \
        const float2 f0 = __half22float2(*(const __half2*)&u.x);              \
        const float2 f1 = __half22float2(*(const __half2*)&u.y);              \
        acc.x = fmaf(w, f0.x, acc.x); acc.y = fmaf(w, f0.y, acc.y);           \
        acc.z = fmaf(w, f1.x, acc.z); acc.w = fmaf(w, f1.y, acc.w);           \
    } while (0)

    int e = beg;
    for (; e + 3 < end; e += 4) {
        const int2 sw0 = g_sorted[e];
        const int2 sw1 = g_sorted[e + 1];
        const int2 sw2 = g_sorted[e + 2];
        const int2 sw3 = g_sorted[e + 3];
        ACC_EDGE(sw0);
        ACC_EDGE(sw1);
        ACC_EDGE(sw2);
        ACC_EDGE(sw3);
    }
    for (; e < end; e++) {
        const int2 sw = g_sorted[e];
        ACC_EDGE(sw);
    }

    const float4 b = ((const float4*)bias)[c];
    float4 r;
    r.x = fmaxf(acc.x + b.x, 0.0f);
    r.y = fmaxf(acc.y + b.y, 0.0f);
    r.z = fmaxf(acc.z + b.z, 0.0f);
    r.w = fmaxf(acc.w + b.w, 0.0f);
    ((float4*)out)[(size_t)d * (UNITS / 4) + c] = r;
}

// ---------------------------------------------------------------------------
extern "C" void kernel_launch(void* const* d_in, const int* in_sizes, int n_in,
                              void* d_out, int out_size)
{
    const float* X    = (const float*)d_in[0];
    const float* W    = (const float*)d_in[1];
    const float* bias = (const float*)d_in[2];
    const float* ew   = (const float*)d_in[3];
    const void*  es   = d_in[4];
    const void*  ed   = d_in[5];
    float* out = (float*)d_out;

    // One-time host-side setup (pre-capture correctness call; no device alloc).
    static cudaStream_t s_csr = nullptr, s_agg = nullptr;
    static cudaEvent_t evFork = nullptr, evCSR = nullptr, evG0 = nullptr, evA0 = nullptr;
    if (!s_csr) {
        cudaStreamCreateWithFlags(&s_csr, cudaStreamNonBlocking);
        cudaStreamCreateWithFlags(&s_agg, cudaStreamNonBlocking);
        cudaEventCreateWithFlags(&evFork, cudaEventDisableTiming);
        cudaEventCreateWithFlags(&evCSR, cudaEventDisableTiming);
        cudaEventCreateWithFlags(&evG0, cudaEventDisableTiming);
        cudaEventCreateWithFlags(&evA0, cudaEventDisableTiming);
        cudaFuncSetAttribute(gemm_mma_kernel,
                             cudaFuncAttributeMaxDynamicSharedMemorySize, GSM);
    }

    // ---- fork ----
    cudaEventRecord(evFork, 0);
    cudaStreamWaitEvent(s_csr, evFork, 0);

    // branch A (s_csr): CSR build
    detect_kernel<<<1, 1, 0, s_csr>>>(es);
    zero_kernel<<<64, 256, 0, s_csr>>>();
    hist_kernel<<<1024, 256, 0, s_csr>>>(ed);
    scan_lookback_kernel<<<SCAN_NB, 256, 0, s_csr>>>();
    place_kernel<<<1024, 256, 0, s_csr>>>(es, ed, ew);
    cudaEventRecord(evCSR, s_csr);

    // branch B (main): fp16 convert + GEMM half 0 (cols 0-255)
    conv_X_kernel<<<2048, 256>>>(X);
    conv_W_kernel<<<256, 256>>>(W);
    gemm_mma_kernel<<<N_PAD / BM, 256, GSM>>>(0);
    cudaEventRecord(evG0, 0);

    // GEMM half 1 (cols 256-511) continues on main
    gemm_mma_kernel<<<N_PAD / BM, 256, GSM>>>(1);

    // branch C (s_agg): aggregate cols 0-255 once GEMM0 + CSR done
    cudaStreamWaitEvent(s_agg, evG0, 0);
    cudaStreamWaitEvent(s_agg, evCSR, 0);
    aggregate_half_kernel<<<N_NODES, 64, 0, s_agg>>>(bias, out, 0);
    cudaEventRecord(evA0, s_agg);

    // main: aggregate cols 256-511 after GEMM1 + CSR, then join branch C
    cudaStreamWaitEvent(0, evCSR, 0);
    aggregate_half_kernel<<<N_NODES, 64>>>(bias, out, 64);
    cudaStreamWaitEvent(0, evA0, 0);
}

// round 12
// speedup vs baseline: 9.0288x; 1.0002x over previous
#include <cuda_runtime.h>
#include <cuda_bf16.h>
#include <cuda_fp16.h>
#include <cstdint>

#define N_NODES 50000
#define N_PAD   50048            // 391 * 128
#define N_EDGES 1600000
#define D_FEAT  512
#define UNITS   512

// ---------------- static device scratch (no runtime allocation) ----------
__device__ __half g_hh[(size_t)N_PAD * UNITS];      // h = X @ W (fp16)
__device__ __half g_Xh[(size_t)N_PAD * D_FEAT];     // X in fp16
__device__ __half g_Wt[(size_t)UNITS * D_FEAT];     // W^T in fp16: [n][k]
__device__ int   g_deg[N_NODES];
__device__ int   g_cursor[N_NODES];
__device__ int   g_off[N_NODES + 1];
__device__ int2  g_sorted[N_EDGES];
__device__ int   g_is64;

#define SCAN_NB 196               // ceil(50000 / 256)
__device__ int g_blk_flag[SCAN_NB];   // 0=invalid 1=aggregate 2=prefix
__device__ int g_blk_agg[SCAN_NB];
__device__ int g_blk_pref[SCAN_NB];

// ---------------- helpers ------------------------------------------------
__device__ __forceinline__ uint32_t smem_u32(const void* p) {
    uint32_t a;
    asm("{ .reg .u64 t; cvta.to.shared.u64 t, %1; cvt.u32.u64 %0, t; }"
        : "=r"(a) : "l"(p));
    return a;
}
__device__ __forceinline__ void cp_async16(uint32_t dst, const void* src) {
    asm volatile("cp.async.cg.shared.global [%0], [%1], 16;" :: "r"(dst), "l"(src));
}
#define CP_COMMIT() asm volatile("cp.async.commit_group;" ::: "memory")
#define CP_WAIT(n)  asm volatile("cp.async.wait_group %0;" :: "n"(n) : "memory")

#define LDMATRIX_X4(r0, r1, r2, r3, addr) \
    asm volatile("ldmatrix.sync.aligned.m8n8.x4.shared.b16 {%0,%1,%2,%3}, [%4];" \
        : "=r"(r0), "=r"(r1), "=r"(r2), "=r"(r3) : "r"(addr))

__device__ __forceinline__ void mma16816_f16(float* d, const uint32_t* a,
                                             uint32_t b0, uint32_t b1) {
    asm volatile(
        "mma.sync.aligned.m16n8k16.row.col.f32.f16.f16.f32 "
        "{%0,%1,%2,%3}, {%4,%5,%6,%7}, {%8,%9}, {%0,%1,%2,%3};"
        : "+f"(d[0]), "+f"(d[1]), "+f"(d[2]), "+f"(d[3])
        : "r"(a[0]), "r"(a[1]), "r"(a[2]), "r"(a[3]), "r"(b0), "r"(b1));
}

// ---------------------------------------------------------------------------
// CSR build
// ---------------------------------------------------------------------------
// Warp-parallel dtype detection: 32 lanes x 2 values each, one ballot.
__global__ void detect_kernel(const void* src_raw)
{
    const long long* p = (const long long*)src_raw;
    const int lane = threadIdx.x;
    const long long v0 = p[lane * 2];
    const long long v1 = p[lane * 2 + 1];
    const bool bad = (v0 < 0) || (v0 >= N_NODES) || (v1 < 0) || (v1 >= N_NODES);
    const unsigned m = __ballot_sync(0xFFFFFFFFu, bad);
    if (lane == 0) g_is64 = (m == 0) ? 1 : 0;
}

__global__ __launch_bounds__(256) void zero_kernel()
{
    const int t = blockIdx.x * blockDim.x + threadIdx.x;
    for (int i = t; i < N_NODES; i += gridDim.x * blockDim.x) {
        g_deg[i] = 0;
        g_cursor[i] = 0;
    }
    if (t < SCAN_NB) g_blk_flag[t] = 0;
    if (t == 0) g_off[N_NODES] = N_EDGES;
}

__global__ __launch_bounds__(256) void hist_kernel(const void* __restrict__ dst_raw)
{
    const int is64 = g_is64;
    for (int i = blockIdx.x * blockDim.x + threadIdx.x;
         i < N_EDGES; i += gridDim.x * blockDim.x) {
        const int d = is64 ? (int)((const long long*)dst_raw)[i]
                           : ((const int*)dst_raw)[i];
        atomicAdd(&g_deg[d], 1);
    }
}

// Decoupled-lookback exclusive scan with WARP-WINDOWED lookback:
// warp 0 inspects 32 predecessors per hop instead of 1.
__global__ __launch_bounds__(256) void scan_lookback_kernel()
{
    __shared__ int warp_sums[8];
    __shared__ int s_base;

    const int b = blockIdx.x;
    const int tid = threadIdx.x;
    const int i = b * 256 + tid;
    const int lane = tid & 31;
    const int w = tid >> 5;

    const int v = (i < N_NODES) ? g_deg[i] : 0;

    int incl = v;
#pragma unroll
    for (int o = 1; o < 32; o <<= 1) {
        int t = __shfl_up_sync(0xFFFFFFFFu, incl, o);
        if (lane >= o) incl += t;
    }
    if (lane == 31) warp_sums[w] = incl;
    __syncthreads();

    if (w == 0) {
        // scan the 8 warp sums
        int ws = (lane < 8) ? warp_sums[lane] : 0;
        int wincl = ws;
#pragma unroll
        for (int o = 1; o < 8; o <<= 1) {
            int t = __shfl_up_sync(0xFFFFFFFFu, wincl, o);
            if (lane >= o) wincl += t;
        }
        if (lane < 8) warp_sums[lane] = wincl - ws;   // exclusive warp base
        const int total = __shfl_sync(0xFFFFFFFFu, wincl, 7);

        volatile int* vflag = g_blk_flag;
        volatile int* vagg  = g_blk_agg;
        volatile int* vpref = g_blk_pref;

        if (b == 0) {
            if (lane == 0) {
                g_blk_agg[0] = total;
                g_blk_pref[0] = total;
                __threadfence();
                vflag[0] = 2;
                s_base = 0;
            }
        } else {
            if (lane == 0) {
                g_blk_agg[b] = total;
                __threadfence();
                vflag[b] = 1;
            }
            int running = 0;
            int p = b - 1;
            while (true) {
                const int idx = p - lane;
                int f;
                do {
                    f = (idx >= 0) ? vflag[idx] : 2;
                } while (__any_sync(0xFFFFFFFFu, f == 0));
                const unsigned pm = __ballot_sync(0xFFFFFFFFu, f == 2);
                const int firstP = __ffs(pm) - 1;   // -1 if no prefix in window
                int contrib = 0;
                if (idx >= 0) {
                    if (pm == 0) {
                        contrib = vagg[idx];
                    } else if (lane < firstP) {
                        contrib = vagg[idx];
                    } else if (lane == firstP) {
                        contrib = vpref[idx];
                    }
                }
#pragma unroll
                for (int o = 16; o > 0; o >>= 1)
                    contrib += __shfl_down_sync(0xFFFFFFFFu, contrib, o);
                contrib = __shfl_sync(0xFFFFFFFFu, contrib, 0);
                running += contrib;
                if (pm != 0) break;
                p -= 32;
            }
            if (lane == 0) {
                s_base = running;
                g_blk_pref[b] = running + total;
                __threadfence();
                vflag[b] = 2;
            }
        }
    }
    __syncthreads();

    if (i < N_NODES)
        g_off[i] = s_base + warp_sums[w] + incl - v;
}

__global__ __launch_bounds__(256) void place_kernel(
    const void* __restrict__ src_raw, const void* __restrict__ dst_raw,
    const float* __restrict__ ew)
{
    const int is64 = g_is64;
    for (int i = blockIdx.x * blockDim.x + threadIdx.x;
         i < N_EDGES; i += gridDim.x * blockDim.x) {
        int s, d;
        if (is64) {
            s = (int)((const long long*)src_raw)[i];
            d = (int)((const long long*)dst_raw)[i];
        } else {
            s = ((const int*)src_raw)[i];
            d = ((const int*)dst_raw)[i];
        }
        const int pos = g_off[d] + atomicAdd(&g_cursor[d], 1);
        g_sorted[pos] = make_int2(s, __float_as_int(ew[i]));
    }
}

// ---------------------------------------------------------------------------
// Prep: fp16 conversion of X (padded rows zeroed) and W^T.
// ---------------------------------------------------------------------------
__global__ __launch_bounds__(256) void conv_X_kernel(const float* __restrict__ X)
{
    const size_t total4 = (size_t)N_PAD * D_FEAT / 4;
    const size_t valid4 = (size_t)N_NODES * D_FEAT / 4;
    for (size_t i = (size_t)blockIdx.x * blockDim.x + threadIdx.x;
         i < total4; i += (size_t)gridDim.x * blockDim.x) {
        float4 x = (i < valid4) ? ((const float4*)X)[i] : make_float4(0.f, 0.f, 0.f, 0.f);
        __half2 h0 = __float22half2_rn(make_float2(x.x, x.y));
        __half2 h1 = __float22half2_rn(make_float2(x.z, x.w));
        ((uint2*)g_Xh)[i] = make_uint2(*(uint32_t*)&h0, *(uint32_t*)&h1);
    }
}

__global__ __launch_bounds__(256) void conv_W_kernel(const float* __restrict__ W)
{
    for (int i = blockIdx.x * blockDim.x + threadIdx.x;
         i < UNITS * D_FEAT; i += gridDim.x * blockDim.x) {
        const int n = i >> 9, k = i & 511;
        g_Wt[i] = __float2half_rn(W[(size_t)k * UNITS + n]);
    }
}

// ---------------------------------------------------------------------------
// fp16 mma.sync GEMM: h = Xh @ Wt^T  (fp32 accumulate, fp16 store)
// CTA tile 128x256x32. Launched per N-column-half (bx passed as param).
// ---------------------------------------------------------------------------
#define BM 128
#define BN 256
#define BK 32
#define PAD 40
#define ABUF (BM * PAD * 2)
#define BBUF (BN * PAD * 2)
#define GSM  (2 * (ABUF + BBUF))    // 61440 B dynamic smem
#define N_ITERS 16                  // 512 / 32

__global__ __launch_bounds__(256, 1) void gemm_mma_kernel(int bx)
{
    extern __shared__ __align__(16) char sm[];
    const uint32_t aSm = smem_u32(sm);
    const uint32_t bSm = aSm + 2 * ABUF;

    const int tid = threadIdx.x;
    const int wid = tid >> 5, lid = tid & 31;
    const int wr = wid >> 2, wc = wid & 3;
    const int by = blockIdx.x;                 // M tile: 0..390

    float acc[4][8][4];
#pragma unroll
    for (int mi = 0; mi < 4; mi++)
#pragma unroll
        for (int nj = 0; nj < 8; nj++)
#pragma unroll
            for (int q = 0; q < 4; q++) acc[mi][nj][q] = 0.0f;

#define LOAD_TILE(it, buf) do {                                                   \
        const int _k0 = (it) * BK;                                                \
        const __half* _Ap = g_Xh + (size_t)(by * BM) * D_FEAT + _k0;              \
        const __half* _Bp = g_Wt + (size_t)(bx * BN) * D_FEAT + _k0;              \
        _Pragma("unroll")                                                         \
        for (int _j = 0; _j < 2; _j++) {                                          \
            const int _p = tid + _j * 256;                                        \
            const int _r = _p >> 2, _c = (_p & 3) * 8;                            \
            cp_async16(aSm + (buf) * ABUF + (uint32_t)(_r * PAD + _c) * 2,        \
                       _Ap + (size_t)_r * D_FEAT + _c);                           \
        }                                                                         \
        _Pragma("unroll")                                                         \
        for (int _j = 0; _j < 4; _j++) {                                          \
            const int _p = tid + _j * 256;                                        \
            const int _r = _p >> 2, _c = (_p & 3) * 8;                            \
            cp_async16(bSm + (buf) * BBUF + (uint32_t)(_r * PAD + _c) * 2,        \
                       _Bp + (size_t)_r * D_FEAT + _c);                           \
        }                                                                         \
        CP_COMMIT();                                                              \
    } while (0)

    LOAD_TILE(0, 0);

    const int lrow = lid & 15;
    const int lcol8 = (lid >> 4) * 8;

#pragma unroll 1
    for (int it = 0; it < N_ITERS; it++) {
        const int b = it & 1;
        if (it + 1 < N_ITERS) {
            LOAD_TILE(it + 1, b ^ 1);
            CP_WAIT(1);
        } else {
            CP_WAIT(0);
        }
        __syncthreads();

#pragma unroll
        for (int ks = 0; ks < BK; ks += 16) {
            uint32_t af[4][4];
#pragma unroll
            for (int mi = 0; mi < 4; mi++) {
                const uint32_t addr = aSm + b * ABUF +
                    (uint32_t)((wr * 64 + mi * 16 + lrow) * PAD + ks + lcol8) * 2;
                LDMATRIX_X4(af[mi][0], af[mi][1], af[mi][2], af[mi][3], addr);
            }
            uint32_t bf[4][4];
#pragma unroll
            for (int nh = 0; nh < 4; nh++) {
                const uint32_t addr = bSm + b * BBUF +
                    (uint32_t)((wc * 64 + nh * 16 + lrow) * PAD + ks + lcol8) * 2;
                LDMATRIX_X4(bf[nh][0], bf[nh][1], bf[nh][2], bf[nh][3], addr);
            }
#pragma unroll
            for (int mi = 0; mi < 4; mi++)
#pragma unroll
                for (int nj = 0; nj < 8; nj++) {
                    const uint32_t b0 = bf[nj >> 1][(nj & 1)];
                    const uint32_t b1 = bf[nj >> 1][(nj & 1) + 2];
                    mma16816_f16(acc[mi][nj], af[mi], b0, b1);
                }
        }
        __syncthreads();
    }

    // epilogue: fp32 accumulators -> fp16 h
    const int qrow = lid >> 2;
    const int qcol = (lid & 3) * 2;
#pragma unroll
    for (int mi = 0; mi < 4; mi++) {
        const size_t r0 = (size_t)by * BM + wr * 64 + mi * 16 + qrow;
#pragma unroll
        for (int nj = 0; nj < 8; nj++) {
            const int c0 = bx * BN + wc * 64 + nj * 8 + qcol;
            *(__half2*)(g_hh + r0 * UNITS + c0) =
                __float22half2_rn(make_float2(acc[mi][nj][0], acc[mi][nj][1]));
            *(__half2*)(g_hh + (r0 + 8) * UNITS + c0) =
                __float22half2_rn(make_float2(acc[mi][nj][2], acc[mi][nj][3]));
        }
    }
}

// ---------------------------------------------------------------------------
// Aggregate over a 256-column half. One block (64 threads) per dst row.
// fp16 gather, fp32 accumulate, fused bias + ReLU. 4-way edge unroll.
// ---------------------------------------------------------------------------
__global__ __launch_bounds__(64) void aggregate_half_kernel(
    const float* __restrict__ bias, float* __restrict__ out, int colbase4)
{
    const int d = blockIdx.x;
    const int c = colbase4 + threadIdx.x;         // uint2 index within row (0..127)
    const int beg = g_off[d];
    const int end = g_off[d + 1];

    const uint2* __restrict__ h2 = (const uint2*)g_hh;   // 128 uint2 per row
    float4 acc = make_float4(0.f, 0.f, 0.f, 0.f);

#define ACC_EDGE(sw) do {                                                     \
        const uint2 u = __ldg(&h2[(size_t)(sw).x * (UNITS / 4) + c]);         \
        const float w = __int_as_float((sw).y);                               \
        const float2 f0 = __half22float2(*(const __half2*)&u.x);              \
        const float2 f1 = __half22float2(*(const __half2*)&u.y);              \
        acc.x = fmaf(w, f0.x, acc.x); acc.y = fmaf(w, f0.y, acc.y);           \
        acc.z = fmaf(w, f1.x, acc.z); acc.w = fmaf(w, f1.y, acc.w);           \
    } while (0)

    int e = beg;
    for (; e + 3 < end; e += 4) {
        const int2 sw0 = g_sorted[e];
        const int2 sw1 = g_sorted[e + 1];
        const int2 sw2 = g_sorted[e + 2];
        const int2 sw3 = g_sorted[e + 3];
        ACC_EDGE(sw0);
        ACC_EDGE(sw1);
        ACC_EDGE(sw2);
        ACC_EDGE(sw3);
    }
    for (; e < end; e++) {
        const int2 sw = g_sorted[e];
        ACC_EDGE(sw);
    }

    const float4 b = ((const float4*)bias)[c];
    float4 r;
    r.x = fmaxf(acc.x + b.x, 0.0f);
    r.y = fmaxf(acc.y + b.y, 0.0f);
    r.z = fmaxf(acc.z + b.z, 0.0f);
    r.w = fmaxf(acc.w + b.w, 0.0f);
    ((float4*)out)[(size_t)d * (UNITS / 4) + c] = r;
}

// ---------------------------------------------------------------------------
extern "C" void kernel_launch(void* const* d_in, const int* in_sizes, int n_in,
                              void* d_out, int out_size)
{
    const float* X    = (const float*)d_in[0];
    const float* W    = (const float*)d_in[1];
    const float* bias = (const float*)d_in[2];
    const float* ew   = (const float*)d_in[3];
    const void*  es   = d_in[4];
    const void*  ed   = d_in[5];
    float* out = (float*)d_out;

    // One-time host-side setup (pre-capture correctness call; no device alloc).
    static cudaStream_t s_csr = nullptr, s_agg = nullptr;
    static cudaEvent_t evFork = nullptr, evCSR = nullptr, evG0 = nullptr,
                       evG1 = nullptr, evA = nullptr;
    if (!s_csr) {
        cudaStreamCreateWithFlags(&s_csr, cudaStreamNonBlocking);
        cudaStreamCreateWithFlags(&s_agg, cudaStreamNonBlocking);
        cudaEventCreateWithFlags(&evFork, cudaEventDisableTiming);
        cudaEventCreateWithFlags(&evCSR, cudaEventDisableTiming);
        cudaEventCreateWithFlags(&evG0, cudaEventDisableTiming);
        cudaEventCreateWithFlags(&evG1, cudaEventDisableTiming);
        cudaEventCreateWithFlags(&evA, cudaEventDisableTiming);
        cudaFuncSetAttribute(gemm_mma_kernel,
                             cudaFuncAttributeMaxDynamicSharedMemorySize, GSM);
    }

    // ---- fork ----
    cudaEventRecord(evFork, 0);
    cudaStreamWaitEvent(s_csr, evFork, 0);
    cudaStreamWaitEvent(s_agg, evFork, 0);

    // branch A (s_csr): CSR build (shortened critical chain)
    detect_kernel<<<1, 32, 0, s_csr>>>(es);
    zero_kernel<<<64, 256, 0, s_csr>>>();
    hist_kernel<<<1024, 256, 0, s_csr>>>(ed);
    scan_lookback_kernel<<<SCAN_NB, 256, 0, s_csr>>>();
    place_kernel<<<1024, 256, 0, s_csr>>>(es, ed, ew);
    cudaEventRecord(evCSR, s_csr);

    // branch B (main): fp16 convert + GEMM halves
    conv_X_kernel<<<2048, 256>>>(X);
    conv_W_kernel<<<256, 256>>>(W);
    gemm_mma_kernel<<<N_PAD / BM, 256, GSM>>>(0);
    cudaEventRecord(evG0, 0);
    gemm_mma_kernel<<<N_PAD / BM, 256, GSM>>>(1);
    cudaEventRecord(evG1, 0);

    // branch C (s_agg): both aggregate halves, sequential (no self-contention)
    cudaStreamWaitEvent(s_agg, evG0, 0);
    cudaStreamWaitEvent(s_agg, evCSR, 0);
    aggregate_half_kernel<<<N_NODES, 64, 0, s_agg>>>(bias, out, 0);
    cudaStreamWaitEvent(s_agg, evG1, 0);
    aggregate_half_kernel<<<N_NODES, 64, 0, s_agg>>>(bias, out, 64);
    cudaEventRecord(evA, s_agg);

    // main joins
    cudaStreamWaitEvent(0, evA, 0);
}

// round 13
// speedup vs baseline: 9.2796x; 1.0278x over previous
#include <cuda_runtime.h>
#include <cuda_bf16.h>
#include <cuda_fp16.h>
#include <cstdint>

#define N_NODES 50000
#define N_PAD   50048            // 391 * 128
#define N_EDGES 1600000
#define D_FEAT  512
#define UNITS   512

// ---------------- static device scratch (no runtime allocation) ----------
__device__ __half g_hh[(size_t)N_PAD * UNITS];      // h = X @ W (fp16)
__device__ __half g_Wt[(size_t)UNITS * D_FEAT];     // W^T in fp16: [n][k]
__device__ int   g_deg[N_NODES];
__device__ int   g_cursor[N_NODES];
__device__ int   g_off[N_NODES + 1];
__device__ int2  g_sorted[N_EDGES];
__device__ int   g_is64;

#define SCAN_NB 196               // ceil(50000 / 256)
__device__ int g_blk_flag[SCAN_NB];   // 0=invalid 1=aggregate 2=prefix
__device__ int g_blk_agg[SCAN_NB];
__device__ int g_blk_pref[SCAN_NB];

// ---------------- helpers ------------------------------------------------
__device__ __forceinline__ uint32_t smem_u32(const void* p) {
    uint32_t a;
    asm("{ .reg .u64 t; cvta.to.shared.u64 t, %1; cvt.u32.u64 %0, t; }"
        : "=r"(a) : "l"(p));
    return a;
}
__device__ __forceinline__ void cp_async16(uint32_t dst, const void* src) {
    asm volatile("cp.async.cg.shared.global [%0], [%1], 16;" :: "r"(dst), "l"(src));
}
#define CP_COMMIT() asm volatile("cp.async.commit_group;" ::: "memory")
#define CP_WAIT(n)  asm volatile("cp.async.wait_group %0;" :: "n"(n) : "memory")

#define LDMATRIX_X4(r0, r1, r2, r3, addr) \
    asm volatile("ldmatrix.sync.aligned.m8n8.x4.shared.b16 {%0,%1,%2,%3}, [%4];" \
        : "=r"(r0), "=r"(r1), "=r"(r2), "=r"(r3) : "r"(addr))

__device__ __forceinline__ void mma16816_f16(float* d, const uint32_t* a,
                                             uint32_t b0, uint32_t b1) {
    asm volatile(
        "mma.sync.aligned.m16n8k16.row.col.f32.f16.f16.f32 "
        "{%0,%1,%2,%3}, {%4,%5,%6,%7}, {%8,%9}, {%0,%1,%2,%3};"
        : "+f"(d[0]), "+f"(d[1]), "+f"(d[2]), "+f"(d[3])
        : "r"(a[0]), "r"(a[1]), "r"(a[2]), "r"(a[3]), "r"(b0), "r"(b1));
}

// ---------------------------------------------------------------------------
// CSR build
// ---------------------------------------------------------------------------
__global__ void detect_kernel(const void* src_raw)
{
    const long long* p = (const long long*)src_raw;
    const int lane = threadIdx.x;
    const long long v0 = p[lane * 2];
    const long long v1 = p[lane * 2 + 1];
    const bool bad = (v0 < 0) || (v0 >= N_NODES) || (v1 < 0) || (v1 >= N_NODES);
    const unsigned m = __ballot_sync(0xFFFFFFFFu, bad);
    if (lane == 0) g_is64 = (m == 0) ? 1 : 0;
}

__global__ __launch_bounds__(256) void zero_kernel()
{
    const int t = blockIdx.x * blockDim.x + threadIdx.x;
    for (int i = t; i < N_NODES; i += gridDim.x * blockDim.x) {
        g_deg[i] = 0;
        g_cursor[i] = 0;
    }
    if (t < SCAN_NB) g_blk_flag[t] = 0;
    if (t == 0) g_off[N_NODES] = N_EDGES;
}

__global__ __launch_bounds__(256) void hist_kernel(const void* __restrict__ dst_raw)
{
    const int is64 = g_is64;
    for (int i = blockIdx.x * blockDim.x + threadIdx.x;
         i < N_EDGES; i += gridDim.x * blockDim.x) {
        const int d = is64 ? (int)((const long long*)dst_raw)[i]
                           : ((const int*)dst_raw)[i];
        atomicAdd(&g_deg[d], 1);
    }
}

// Decoupled-lookback exclusive scan with warp-windowed lookback.
__global__ __launch_bounds__(256) void scan_lookback_kernel()
{
    __shared__ int warp_sums[8];
    __shared__ int s_base;

    const int b = blockIdx.x;
    const int tid = threadIdx.x;
    const int i = b * 256 + tid;
    const int lane = tid & 31;
    const int w = tid >> 5;

    const int v = (i < N_NODES) ? g_deg[i] : 0;

    int incl = v;
#pragma unroll
    for (int o = 1; o < 32; o <<= 1) {
        int t = __shfl_up_sync(0xFFFFFFFFu, incl, o);
        if (lane >= o) incl += t;
    }
    if (lane == 31) warp_sums[w] = incl;
    __syncthreads();

    if (w == 0) {
        int ws = (lane < 8) ? warp_sums[lane] : 0;
        int wincl = ws;
#pragma unroll
        for (int o = 1; o < 8; o <<= 1) {
            int t = __shfl_up_sync(0xFFFFFFFFu, wincl, o);
            if (lane >= o) wincl += t;
        }
        if (lane < 8) warp_sums[lane] = wincl - ws;
        const int total = __shfl_sync(0xFFFFFFFFu, wincl, 7);

        volatile int* vflag = g_blk_flag;
        volatile int* vagg  = g_blk_agg;
        volatile int* vpref = g_blk_pref;

        if (b == 0) {
            if (lane == 0) {
                g_blk_agg[0] = total;
                g_blk_pref[0] = total;
                __threadfence();
                vflag[0] = 2;
                s_base = 0;
            }
        } else {
            if (lane == 0) {
                g_blk_agg[b] = total;
                __threadfence();
                vflag[b] = 1;
            }
            int running = 0;
            int p = b - 1;
            while (true) {
                const int idx = p - lane;
                int f;
                do {
                    f = (idx >= 0) ? vflag[idx] : 2;
                } while (__any_sync(0xFFFFFFFFu, f == 0));
                const unsigned pm = __ballot_sync(0xFFFFFFFFu, f == 2);
                const int firstP = __ffs(pm) - 1;
                int contrib = 0;
                if (idx >= 0) {
                    if (pm == 0) {
                        contrib = vagg[idx];
                    } else if (lane < firstP) {
                        contrib = vagg[idx];
                    } else if (lane == firstP) {
                        contrib = vpref[idx];
                    }
                }
#pragma unroll
                for (int o = 16; o > 0; o >>= 1)
                    contrib += __shfl_down_sync(0xFFFFFFFFu, contrib, o);
                contrib = __shfl_sync(0xFFFFFFFFu, contrib, 0);
                running += contrib;
                if (pm != 0) break;
                p -= 32;
            }
            if (lane == 0) {
                s_base = running;
                g_blk_pref[b] = running + total;
                __threadfence();
                vflag[b] = 2;
            }
        }
    }
    __syncthreads();

    if (i < N_NODES)
        g_off[i] = s_base + warp_sums[w] + incl - v;
}

__global__ __launch_bounds__(256) void place_kernel(
    const void* __restrict__ src_raw, const void* __restrict__ dst_raw,
    const float* __restrict__ ew)
{
    const int is64 = g_is64;
    for (int i = blockIdx.x * blockDim.x + threadIdx.x;
         i < N_EDGES; i += gridDim.x * blockDim.x) {
        int s, d;
        if (is64) {
            s = (int)((const long long*)src_raw)[i];
            d = (int)((const long long*)dst_raw)[i];
        } else {
            s = ((const int*)src_raw)[i];
            d = ((const int*)dst_raw)[i];
        }
        const int pos = g_off[d] + atomicAdd(&g_cursor[d], 1);
        g_sorted[pos] = make_int2(s, __float_as_int(ew[i]));
    }
}

// ---------------------------------------------------------------------------
// Prep: W^T fp16 (tiny; X conversion is fused into the GEMM).
// ---------------------------------------------------------------------------
__global__ __launch_bounds__(256) void conv_W_kernel(const float* __restrict__ W)
{
    for (int i = blockIdx.x * blockDim.x + threadIdx.x;
         i < UNITS * D_FEAT; i += gridDim.x * blockDim.x) {
        const int n = i >> 9, k = i & 511;
        g_Wt[i] = __float2half_rn(W[(size_t)k * UNITS + n]);
    }
}

// ---------------------------------------------------------------------------
// fp16 mma.sync GEMM with fused fp32->fp16 A conversion.
// h = X @ Wt^T  (fp32 accumulate, fp16 store). CTA tile 128x256x32.
// A: LDG.128 fp32 register prefetch -> convert -> STS fp16 (PAD-pitch smem).
// B: cp.async fp16 double-buffered (g_Wt).
// ---------------------------------------------------------------------------
#define BM 128
#define BN 256
#define BK 32
#define PAD 40
#define ABUF (BM * PAD * 2)         // 10240 B per A stage
#define BBUF (BN * PAD * 2)         // 20480 B per B stage
#define GSM  (2 * (ABUF + BBUF))    // 61440 B dynamic smem
#define N_ITERS 16                  // 512 / 32

__global__ __launch_bounds__(256, 1) void gemm_mma_kernel(
    const float* __restrict__ X, int bx)
{
    extern __shared__ __align__(16) char sm[];
    const uint32_t aSm = smem_u32(sm);
    const uint32_t bSm = aSm + 2 * ABUF;

    const int tid = threadIdx.x;
    const int wid = tid >> 5, lid = tid & 31;
    const int wr = wid >> 2, wc = wid & 3;
    const int by = blockIdx.x;                 // M tile: 0..390

    float acc[4][8][4];
#pragma unroll
    for (int mi = 0; mi < 4; mi++)
#pragma unroll
        for (int nj = 0; nj < 8; nj++)
#pragma unroll
            for (int q = 0; q < 4; q++) acc[mi][nj][q] = 0.0f;

    // A piece mapping: 1024 float4 pieces per stage, 4 per thread.
    // piece p: row = p>>3 (0..127), col = (p&7)*4 within the 32-col chunk.
    float4 aReg[4];

#define LDG_A(it) do {                                                            \
        const int _k0 = (it) * BK;                                                \
        _Pragma("unroll")                                                         \
        for (int _j = 0; _j < 4; _j++) {                                          \
            const int _p = tid + _j * 256;                                        \
            const int _r = _p >> 3, _c = (_p & 7) * 4;                            \
            const int _gr = by * BM + _r;                                         \
            aReg[_j] = (_gr < N_NODES)                                            \
                ? *(const float4*)(X + (size_t)_gr * D_FEAT + _k0 + _c)           \
                : make_float4(0.f, 0.f, 0.f, 0.f);                                \
        }                                                                         \
    } while (0)

#define STS_A(buf) do {                                                           \
        _Pragma("unroll")                                                         \
        for (int _j = 0; _j < 4; _j++) {                                          \
            const int _p = tid + _j * 256;                                        \
            const int _r = _p >> 3, _c = (_p & 7) * 4;                            \
            __half2 _h0 = __float22half2_rn(make_float2(aReg[_j].x, aReg[_j].y)); \
            __half2 _h1 = __float22half2_rn(make_float2(aReg[_j].z, aReg[_j].w)); \
            *(uint2*)(sm + (buf) * ABUF + (uint32_t)(_r * PAD + _c) * 2) =        \
                make_uint2(*(uint32_t*)&_h0, *(uint32_t*)&_h1);                   \
        }                                                                         \
    } while (0)

#define LOAD_B(it, buf) do {                                                      \
        const int _k0 = (it) * BK;                                                \
        const __half* _Bp = g_Wt + (size_t)(bx * BN) * D_FEAT + _k0;              \
        _Pragma("unroll")                                                         \
        for (int _j = 0; _j < 4; _j++) {                                          \
            const int _p = tid + _j * 256;                                        \
            const int _r = _p >> 2, _c = (_p & 3) * 8;                            \
            cp_async16(bSm + (buf) * BBUF + (uint32_t)(_r * PAD + _c) * 2,        \
                       _Bp + (size_t)_r * D_FEAT + _c);                           \
        }                                                                         \
        CP_COMMIT();                                                              \
    } while (0)

    LDG_A(0);
    LOAD_B(0, 0);

    const int lrow = lid & 15;
    const int lcol8 = (lid >> 4) * 8;

#pragma unroll 1
    for (int it = 0; it < N_ITERS; it++) {
        const int b = it & 1;
        STS_A(b);                              // A chunk 'it' (regs) -> smem
        if (it + 1 < N_ITERS) {
            LDG_A(it + 1);                     // prefetch next A into regs
            LOAD_B(it + 1, b ^ 1);             // prefetch next B via cp.async
            CP_WAIT(1);                        // B chunk 'it' has landed
        } else {
            CP_WAIT(0);
        }
        __syncthreads();

#pragma unroll
        for (int ks = 0; ks < BK; ks += 16) {
            uint32_t af[4][4];
#pragma unroll
            for (int mi = 0; mi < 4; mi++) {
                const uint32_t addr = aSm + b * ABUF +
                    (uint32_t)((wr * 64 + mi * 16 + lrow) * PAD + ks + lcol8) * 2;
                LDMATRIX_X4(af[mi][0], af[mi][1], af[mi][2], af[mi][3], addr);
            }
            uint32_t bf[4][4];
#pragma unroll
            for (int nh = 0; nh < 4; nh++) {
                const uint32_t addr = bSm + b * BBUF +
                    (uint32_t)((wc * 64 + nh * 16 + lrow) * PAD + ks + lcol8) * 2;
                LDMATRIX_X4(bf[nh][0], bf[nh][1], bf[nh][2], bf[nh][3], addr);
            }
#pragma unroll
            for (int mi = 0; mi < 4; mi++)
#pragma unroll
                for (int nj = 0; nj < 8; nj++) {
                    const uint32_t b0 = bf[nj >> 1][(nj & 1)];
                    const uint32_t b1 = bf[nj >> 1][(nj & 1) + 2];
                    mma16816_f16(acc[mi][nj], af[mi], b0, b1);
                }
        }
        __syncthreads();
    }

    // epilogue: fp32 accumulators -> fp16 h
    const int qrow = lid >> 2;
    const int qcol = (lid & 3) * 2;
#pragma unroll
    for (int mi = 0; mi < 4; mi++) {
        const size_t r0 = (size_t)by * BM + wr * 64 + mi * 16 + qrow;
#pragma unroll
        for (int nj = 0; nj < 8; nj++) {
            const int c0 = bx * BN + wc * 64 + nj * 8 + qcol;
            *(__half2*)(g_hh + r0 * UNITS + c0) =
                __float22half2_rn(make_float2(acc[mi][nj][0], acc[mi][nj][1]));
            *(__half2*)(g_hh + (r0 + 8) * UNITS + c0) =
                __float22half2_rn(make_float2(acc[mi][nj][2], acc[mi][nj][3]));
        }
    }
}

// ---------------------------------------------------------------------------
// Aggregate over a 256-column half. One block (64 threads) per dst row.
// fp16 gather, fp32 accumulate, fused bias + ReLU. 8-way edge unroll.
// ---------------------------------------------------------------------------
__global__ __launch_bounds__(64) void aggregate_half_kernel(
    const float* __restrict__ bias, float* __restrict__ out, int colbase4)
{
    const int d = blockIdx.x;
    const int c = colbase4 + threadIdx.x;         // uint2 index within row
    const int beg = g_off[d];
    const int end = g_off[d + 1];

    const uint2* __restrict__ h2 = (const uint2*)g_hh;   // 128 uint2 per row
    float4 acc = make_float4(0.f, 0.f, 0.f, 0.f);

#define ACC_EDGE(sw) do {                                                     \
        const uint2 u = __ldg(&h2[(size_t)(sw).x * (UNITS / 4) + c]);         \
        const float w = __int_as_float((sw).y);                               \
        const float2 f0 = __half22float2(*(const __half2*)&u.x);              \
        const float2 f1 = __half22float2(*(const __half2*)&u.y);              \
        acc.x = fmaf(w, f0.x, acc.x); acc.y = fmaf(w, f0.y, acc.y);           \
        acc.z = fmaf(w, f1.x, acc.z); acc.w = fmaf(w, f1.y, acc.w);           \
    } while (0)

    int e = beg;
    for (; e + 7 < end; e += 8) {
        int2 sw[8];
#pragma unroll
        for (int q = 0; q < 8; q++) sw[q] = g_sorted[e + q];
#pragma unroll
        for (int q = 0; q < 8; q++) ACC_EDGE(sw[q]);
    }
    for (; e + 3 < end; e += 4) {
        int2 sw[4];
#pragma unroll
        for (int q = 0; q < 4; q++) sw[q] = g_sorted[e + q];
#pragma unroll
        for (int q = 0; q < 4; q++) ACC_EDGE(sw[q]);
    }
    for (; e < end; e++) {
        const int2 sw = g_sorted[e];
        ACC_EDGE(sw);
    }

    const float4 b = ((const float4*)bias)[c];
    float4 r;
    r.x = fmaxf(acc.x + b.x, 0.0f);
    r.y = fmaxf(acc.y + b.y, 0.0f);
    r.z = fmaxf(acc.z + b.z, 0.0f);
    r.w = fmaxf(acc.w + b.w, 0.0f);
    ((float4*)out)[(size_t)d * (UNITS / 4) + c] = r;
}

// ---------------------------------------------------------------------------
extern "C" void kernel_launch(void* const* d_in, const int* in_sizes, int n_in,
                              void* d_out, int out_size)
{
    const float* X    = (const float*)d_in[0];
    const float* W    = (const float*)d_in[1];
    const float* bias = (const float*)d_in[2];
    const float* ew   = (const float*)d_in[3];
    const void*  es   = d_in[4];
    const void*  ed   = d_in[5];
    float* out = (float*)d_out;

    // One-time host-side setup (pre-capture correctness call; no device alloc).
    static cudaStream_t s_csr = nullptr, s_agg = nullptr;
    static cudaEvent_t evFork = nullptr, evCSR = nullptr, evG0 = nullptr,
                       evG1 = nullptr, evA = nullptr;
    if (!s_csr) {
        cudaStreamCreateWithFlags(&s_csr, cudaStreamNonBlocking);
        cudaStreamCreateWithFlags(&s_agg, cudaStreamNonBlocking);
        cudaEventCreateWithFlags(&evFork, cudaEventDisableTiming);
        cudaEventCreateWithFlags(&evCSR, cudaEventDisableTiming);
        cudaEventCreateWithFlags(&evG0, cudaEventDisableTiming);
        cudaEventCreateWithFlags(&evG1, cudaEventDisableTiming);
        cudaEventCreateWithFlags(&evA, cudaEventDisableTiming);
        cudaFuncSetAttribute(gemm_mma_kernel,
                             cudaFuncAttributeMaxDynamicSharedMemorySize, GSM);
    }

    // ---- fork ----
    cudaEventRecord(evFork, 0);
    cudaStreamWaitEvent(s_csr, evFork, 0);
    cudaStreamWaitEvent(s_agg, evFork, 0);

    // branch A (s_csr): CSR build
    detect_kernel<<<1, 32, 0, s_csr>>>(es);
    zero_kernel<<<64, 256, 0, s_csr>>>();
    hist_kernel<<<1024, 256, 0, s_csr>>>(ed);
    scan_lookback_kernel<<<SCAN_NB, 256, 0, s_csr>>>();
    place_kernel<<<1024, 256, 0, s_csr>>>(es, ed, ew);
    cudaEventRecord(evCSR, s_csr);

    // branch B (main): tiny W convert, then GEMM halves (A conv fused in)
    conv_W_kernel<<<256, 256>>>(W);
    gemm_mma_kernel<<<N_PAD / BM, 256, GSM>>>(X, 0);
    cudaEventRecord(evG0, 0);
    gemm_mma_kernel<<<N_PAD / BM, 256, GSM>>>(X, 1);
    cudaEventRecord(evG1, 0);

    // branch C (s_agg): aggregate halves, sequential
    cudaStreamWaitEvent(s_agg, evG0, 0);
    cudaStreamWaitEvent(s_agg, evCSR, 0);
    aggregate_half_kernel<<<N_NODES, 64, 0, s_agg>>>(bias, out, 0);
    cudaStreamWaitEvent(s_agg, evG1, 0);
    aggregate_half_kernel<<<N_NODES, 64, 0, s_agg>>>(bias, out, 64);
    cudaEventRecord(evA, s_agg);

    // main joins
    cudaStreamWaitEvent(0, evA, 0);
}

// round 14
// speedup vs baseline: 9.5425x; 1.0283x over previous
#include <cuda_runtime.h>
#include <cuda_bf16.h>
#include <cuda_fp16.h>
#include <cstdint>

#define N_NODES 50000
#define N_PAD   50048            // 391 * 128
#define N_EDGES 1600000
#define D_FEAT  512
#define UNITS   512

// ---------------- static device scratch (no runtime allocation) ----------
__device__ __half g_hh[(size_t)N_PAD * UNITS];      // h = X @ W (fp16)
__device__ __half g_Wt[(size_t)UNITS * D_FEAT];     // W^T in fp16: [n][k]
__device__ int   g_deg[N_NODES];
__device__ int   g_cursor[N_NODES];
__device__ int   g_off[N_NODES + 1];
__device__ int2  g_sorted[N_EDGES];

#define SCAN_T  512
#define SCAN_NB 98                // ceil(50000 / 512)
__device__ int g_blk_flag[SCAN_NB];   // 0=invalid 1=aggregate 2=prefix
__device__ int g_blk_agg[SCAN_NB];
__device__ int g_blk_pref[SCAN_NB];

// ---------------- helpers ------------------------------------------------
__device__ __forceinline__ uint32_t smem_u32(const void* p) {
    uint32_t a;
    asm("{ .reg .u64 t; cvta.to.shared.u64 t, %1; cvt.u32.u64 %0, t; }"
        : "=r"(a) : "l"(p));
    return a;
}
__device__ __forceinline__ void cp_async16(uint32_t dst, const void* src) {
    asm volatile("cp.async.cg.shared.global [%0], [%1], 16;" :: "r"(dst), "l"(src));
}
#define CP_COMMIT() asm volatile("cp.async.commit_group;" ::: "memory")
#define CP_WAIT(n)  asm volatile("cp.async.wait_group %0;" :: "n"(n) : "memory")

#define LDMATRIX_X4(r0, r1, r2, r3, addr) \
    asm volatile("ldmatrix.sync.aligned.m8n8.x4.shared.b16 {%0,%1,%2,%3}, [%4];" \
        : "=r"(r0), "=r"(r1), "=r"(r2), "=r"(r3) : "r"(addr))

__device__ __forceinline__ void mma16816_f16(float* d, const uint32_t* a,
                                             uint32_t b0, uint32_t b1) {
    asm volatile(
        "mma.sync.aligned.m16n8k16.row.col.f32.f16.f16.f32 "
        "{%0,%1,%2,%3}, {%4,%5,%6,%7}, {%8,%9}, {%0,%1,%2,%3};"
        : "+f"(d[0]), "+f"(d[1]), "+f"(d[2]), "+f"(d[3])
        : "r"(a[0]), "r"(a[1]), "r"(a[2]), "r"(a[3]), "r"(b0), "r"(b1));
}

// Per-block int64/int32 detection (warp 0, broadcast via smem). First block
// pays one 512B read; later blocks hit L2.
__device__ __forceinline__ int block_detect_is64(const void* src_raw) {
    __shared__ int s_is64;
    if (threadIdx.x < 32) {
        const long long* p = (const long long*)src_raw;
        const long long v0 = p[threadIdx.x * 2];
        const long long v1 = p[threadIdx.x * 2 + 1];
        const bool bad = (v0 < 0) || (v0 >= N_NODES) || (v1 < 0) || (v1 >= N_NODES);
        const unsigned m = __ballot_sync(0xFFFFFFFFu, bad);
        if (threadIdx.x == 0) s_is64 = (m == 0) ? 1 : 0;
    }
    __syncthreads();
    return s_is64;
}

// ---------------------------------------------------------------------------
// CSR build
// ---------------------------------------------------------------------------
__global__ __launch_bounds__(256) void zero_kernel()
{
    const int t = blockIdx.x * blockDim.x + threadIdx.x;
    for (int i = t; i < N_NODES; i += gridDim.x * blockDim.x) {
        g_deg[i] = 0;
        g_cursor[i] = 0;
    }
    if (t < SCAN_NB) g_blk_flag[t] = 0;
    if (t == 0) g_off[N_NODES] = N_EDGES;
}

// Histogram: 4 edges per thread-iteration, vectorized loads.
__global__ __launch_bounds__(256) void hist_kernel(const void* __restrict__ dst_raw)
{
    const int is64 = block_detect_is64(dst_raw);
    const int nquad = N_EDGES / 4;           // 400000 (exact)
    for (int i = blockIdx.x * blockDim.x + threadIdx.x;
         i < nquad; i += gridDim.x * blockDim.x) {
        int d0, d1, d2, d3;
        if (is64) {
            const longlong2 a = ((const longlong2*)dst_raw)[2 * i];
            const longlong2 b = ((const longlong2*)dst_raw)[2 * i + 1];
            d0 = (int)a.x; d1 = (int)a.y; d2 = (int)b.x; d3 = (int)b.y;
        } else {
            const int4 q = ((const int4*)dst_raw)[i];
            d0 = q.x; d1 = q.y; d2 = q.z; d3 = q.w;
        }
        atomicAdd(&g_deg[d0], 1);
        atomicAdd(&g_deg[d1], 1);
        atomicAdd(&g_deg[d2], 1);
        atomicAdd(&g_deg[d3], 1);
    }
}

// Decoupled-lookback exclusive scan, 512 threads x 98 blocks,
// warp-windowed lookback.
__global__ __launch_bounds__(SCAN_T) void scan_lookback_kernel()
{
    __shared__ int warp_sums[16];
    __shared__ int s_base;

    const int b = blockIdx.x;
    const int tid = threadIdx.x;
    const int i = b * SCAN_T + tid;
    const int lane = tid & 31;
    const int w = tid >> 5;

    const int v = (i < N_NODES) ? g_deg[i] : 0;

    int incl = v;
#pragma unroll
    for (int o = 1; o < 32; o <<= 1) {
        int t = __shfl_up_sync(0xFFFFFFFFu, incl, o);
        if (lane >= o) incl += t;
    }
    if (lane == 31) warp_sums[w] = incl;
    __syncthreads();

    if (w == 0) {
        int ws = (lane < 16) ? warp_sums[lane] : 0;
        int wincl = ws;
#pragma unroll
        for (int o = 1; o < 16; o <<= 1) {
            int t = __shfl_up_sync(0xFFFFFFFFu, wincl, o);
            if (lane >= o) wincl += t;
        }
        if (lane < 16) warp_sums[lane] = wincl - ws;   // exclusive warp base
        const int total = __shfl_sync(0xFFFFFFFFu, wincl, 15);

        volatile int* vflag = g_blk_flag;
        volatile int* vagg  = g_blk_agg;
        volatile int* vpref = g_blk_pref;

        if (b == 0) {
            if (lane == 0) {
                g_blk_agg[0] = total;
                g_blk_pref[0] = total;
                __threadfence();
                vflag[0] = 2;
                s_base = 0;
            }
        } else {
            if (lane == 0) {
                g_blk_agg[b] = total;
                __threadfence();
                vflag[b] = 1;
            }
            int running = 0;
            int p = b - 1;
            while (true) {
                const int idx = p - lane;
                int f;
                do {
                    f = (idx >= 0) ? vflag[idx] : 2;
                } while (__any_sync(0xFFFFFFFFu, f == 0));
                const unsigned pm = __ballot_sync(0xFFFFFFFFu, f == 2);
                const int firstP = __ffs(pm) - 1;
                int contrib = 0;
                if (idx >= 0) {
                    if (pm == 0) {
                        contrib = vagg[idx];
                    } else if (lane < firstP) {
                        contrib = vagg[idx];
                    } else if (lane == firstP) {
                        contrib = vpref[idx];
                    }
                }
#pragma unroll
                for (int o = 16; o > 0; o >>= 1)
                    contrib += __shfl_down_sync(0xFFFFFFFFu, contrib, o);
                contrib = __shfl_sync(0xFFFFFFFFu, contrib, 0);
                running += contrib;
                if (pm != 0) break;
                p -= 32;
            }
            if (lane == 0) {
                s_base = running;
                g_blk_pref[b] = running + total;
                __threadfence();
                vflag[b] = 2;
            }
        }
    }
    __syncthreads();

    if (i < N_NODES)
        g_off[i] = s_base + warp_sums[w] + incl - v;
}

// Placement: 2 edges per thread-iteration, vectorized loads.
__global__ __launch_bounds__(256) void place_kernel(
    const void* __restrict__ src_raw, const void* __restrict__ dst_raw,
    const float* __restrict__ ew)
{
    const int is64 = block_detect_is64(src_raw);
    const int npair = N_EDGES / 2;           // 800000 (exact)
    for (int i = blockIdx.x * blockDim.x + threadIdx.x;
         i < npair; i += gridDim.x * blockDim.x) {
        int s0, s1, d0, d1;
        if (is64) {
            const longlong2 sv = ((const longlong2*)src_raw)[i];
            const longlong2 dv = ((const longlong2*)dst_raw)[i];
            s0 = (int)sv.x; s1 = (int)sv.y;
            d0 = (int)dv.x; d1 = (int)dv.y;
        } else {
            const int2 sv = ((const int2*)src_raw)[i];
            const int2 dv = ((const int2*)dst_raw)[i];
            s0 = sv.x; s1 = sv.y;
            d0 = dv.x; d1 = dv.y;
        }
        const float2 wv = ((const float2*)ew)[i];
        const int p0 = g_off[d0] + atomicAdd(&g_cursor[d0], 1);
        g_sorted[p0] = make_int2(s0, __float_as_int(wv.x));
        const int p1 = g_off[d1] + atomicAdd(&g_cursor[d1], 1);
        g_sorted[p1] = make_int2(s1, __float_as_int(wv.y));
    }
}

// ---------------------------------------------------------------------------
// Prep: W^T fp16 (tiny; X conversion is fused into the GEMM).
// ---------------------------------------------------------------------------
__global__ __launch_bounds__(256) void conv_W_kernel(const float* __restrict__ W)
{
    for (int i = blockIdx.x * blockDim.x + threadIdx.x;
         i < UNITS * D_FEAT; i += gridDim.x * blockDim.x) {
        const int n = i >> 9, k = i & 511;
        g_Wt[i] = __float2half_rn(W[(size_t)k * UNITS + n]);
    }
}

// ---------------------------------------------------------------------------
// fp16 mma.sync GEMM with fused fp32->fp16 A conversion.
// h = X @ Wt^T  (fp32 accumulate, fp16 store). CTA tile 128x256x32.
// ---------------------------------------------------------------------------
#define BM 128
#define BN 256
#define BK 32
#define PAD 40
#define ABUF (BM * PAD * 2)
#define BBUF (BN * PAD * 2)
#define GSM  (2 * (ABUF + BBUF))    // 61440 B dynamic smem
#define N_ITERS 16                  // 512 / 32

__global__ __launch_bounds__(256, 1) void gemm_mma_kernel(
    const float* __restrict__ X, int bx)
{
    extern __shared__ __align__(16) char sm[];
    const uint32_t aSm = smem_u32(sm);
    const uint32_t bSm = aSm + 2 * ABUF;

    const int tid = threadIdx.x;
    const int wid = tid >> 5, lid = tid & 31;
    const int wr = wid >> 2, wc = wid & 3;
    const int by = blockIdx.x;                 // M tile: 0..390

    float acc[4][8][4];
#pragma unroll
    for (int mi = 0; mi < 4; mi++)
#pragma unroll
        for (int nj = 0; nj < 8; nj++)
#pragma unroll
            for (int q = 0; q < 4; q++) acc[mi][nj][q] = 0.0f;

    float4 aReg[4];

#define LDG_A(it) do {                                                            \
        const int _k0 = (it) * BK;                                                \
        _Pragma("unroll")                                                         \
        for (int _j = 0; _j < 4; _j++) {                                          \
            const int _p = tid + _j * 256;                                        \
            const int _r = _p >> 3, _c = (_p & 7) * 4;                            \
            const int _gr = by * BM + _r;                                         \
            aReg[_j] = (_gr < N_NODES)                                            \
                ? *(const float4*)(X + (size_t)_gr * D_FEAT + _k0 + _c)           \
                : make_float4(0.f, 0.f, 0.f, 0.f);                                \
        }                                                                         \
    } while (0)

#define STS_A(buf) do {                                                           \
        _Pragma("unroll")                                                         \
        for (int _j = 0; _j < 4; _j++) {                                          \
            const int _p = tid + _j * 256;                                        \
            const int _r = _p >> 3, _c = (_p & 7) * 4;                            \
            __half2 _h0 = __float22half2_rn(make_float2(aReg[_j].x, aReg[_j].y)); \
            __half2 _h1 = __float22half2_rn(make_float2(aReg[_j].z, aReg[_j].w)); \
            *(uint2*)(sm + (buf) * ABUF + (uint32_t)(_r * PAD + _c) * 2) =        \
                make_uint2(*(uint32_t*)&_h0, *(uint32_t*)&_h1);                   \
        }                                                                         \
    } while (0)

#define LOAD_B(it, buf) do {                                                      \
        const int _k0 = (it) * BK;                                                \
        const __half* _Bp = g_Wt + (size_t)(bx * BN) * D_FEAT + _k0;              \
        _Pragma("unroll")                                                         \
        for (int _j = 0; _j < 4; _j++) {                                          \
            const int _p = tid + _j * 256;                                        \
            const int _r = _p >> 2, _c = (_p & 3) * 8;                            \
            cp_async16(bSm + (buf) * BBUF + (uint32_t)(_r * PAD + _c) * 2,        \
                       _Bp + (size_t)_r * D_FEAT + _c);                           \
        }                                                                         \
        CP_COMMIT();                                                              \
    } while (0)

    LDG_A(0);
    LOAD_B(0, 0);

    const int lrow = lid & 15;
    const int lcol8 = (lid >> 4) * 8;

#pragma unroll 1
    for (int it = 0; it < N_ITERS; it++) {
        const int b = it & 1;
        STS_A(b);
        if (it + 1 < N_ITERS) {
            LDG_A(it + 1);
            LOAD_B(it + 1, b ^ 1);
            CP_WAIT(1);
        } else {
            CP_WAIT(0);
        }
        __syncthreads();

#pragma unroll
        for (int ks = 0; ks < BK; ks += 16) {
            uint32_t af[4][4];
#pragma unroll
            for (int mi = 0; mi < 4; mi++) {
                const uint32_t addr = aSm + b * ABUF +
                    (uint32_t)((wr * 64 + mi * 16 + lrow) * PAD + ks + lcol8) * 2;
                LDMATRIX_X4(af[mi][0], af[mi][1], af[mi][2], af[mi][3], addr);
            }
            uint32_t bf[4][4];
#pragma unroll
            for (int nh = 0; nh < 4; nh++) {
                const uint32_t addr = bSm + b * BBUF +
                    (uint32_t)((wc * 64 + nh * 16 + lrow) * PAD + ks + lcol8) * 2;
                LDMATRIX_X4(bf[nh][0], bf[nh][1], bf[nh][2], bf[nh][3], addr);
            }
#pragma unroll
            for (int mi = 0; mi < 4; mi++)
#pragma unroll
                for (int nj = 0; nj < 8; nj++) {
                    const uint32_t b0 = bf[nj >> 1][(nj & 1)];
                    const uint32_t b1 = bf[nj >> 1][(nj & 1) + 2];
                    mma16816_f16(acc[mi][nj], af[mi], b0, b1);
                }
        }
        __syncthreads();
    }

    const int qrow = lid >> 2;
    const int qcol = (lid & 3) * 2;
#pragma unroll
    for (int mi = 0; mi < 4; mi++) {
        const size_t r0 = (size_t)by * BM + wr * 64 + mi * 16 + qrow;
#pragma unroll
        for (int nj = 0; nj < 8; nj++) {
            const int c0 = bx * BN + wc * 64 + nj * 8 + qcol;
            *(__half2*)(g_hh + r0 * UNITS + c0) =
                __float22half2_rn(make_float2(acc[mi][nj][0], acc[mi][nj][1]));
            *(__half2*)(g_hh + (r0 + 8) * UNITS + c0) =
                __float22half2_rn(make_float2(acc[mi][nj][2], acc[mi][nj][3]));
        }
    }
}

// ---------------------------------------------------------------------------
// Aggregate over a 256-column half. One block (64 threads) per dst row.
// fp16 gather, fp32 accumulate, fused bias + ReLU. 8-way edge unroll.
// ---------------------------------------------------------------------------
__global__ __launch_bounds__(64) void aggregate_half_kernel(
    const float* __restrict__ bias, float* __restrict__ out, int colbase4)
{
    const int d = blockIdx.x;
    const int c = colbase4 + threadIdx.x;
    const int beg = g_off[d];
    const int end = g_off[d + 1];

    const uint2* __restrict__ h2 = (const uint2*)g_hh;
    float4 acc = make_float4(0.f, 0.f, 0.f, 0.f);

#define ACC_EDGE(sw) do {                                                     \
        const uint2 u = __ldg(&h2[(size_t)(sw).x * (UNITS / 4) + c]);         \
        const float w = __int_as_float((sw).y);                               \
        const float2 f0 = __half22float2(*(const __half2*)&u.x);              \
        const float2 f1 = __half22float2(*(const __half2*)&u.y);              \
        acc.x = fmaf(w, f0.x, acc.x); acc.y = fmaf(w, f0.y, acc.y);           \
        acc.z = fmaf(w, f1.x, acc.z); acc.w = fmaf(w, f1.y, acc.w);           \
    } while (0)

    int e = beg;
    for (; e + 7 < end; e += 8) {
        int2 sw[8];
#pragma unroll
        for (int q = 0; q < 8; q++) sw[q] = g_sorted[e + q];
#pragma unroll
        for (int q = 0; q < 8; q++) ACC_EDGE(sw[q]);
    }
    for (; e + 3 < end; e += 4) {
        int2 sw[4];
#pragma unroll
        for (int q = 0; q < 4; q++) sw[q] = g_sorted[e + q];
#pragma unroll
        for (int q = 0; q < 4; q++) ACC_EDGE(sw[q]);
    }
    for (; e < end; e++) {
        const int2 sw = g_sorted[e];
        ACC_EDGE(sw);
    }

    const float4 b = ((const float4*)bias)[c];
    float4 r;
    r.x = fmaxf(acc.x + b.x, 0.0f);
    r.y = fmaxf(acc.y + b.y, 0.0f);
    r.z = fmaxf(acc.z + b.z, 0.0f);
    r.w = fmaxf(acc.w + b.w, 0.0f);
    ((float4*)out)[(size_t)d * (UNITS / 4) + c] = r;
}

// ---------------------------------------------------------------------------
extern "C" void kernel_launch(void* const* d_in, const int* in_sizes, int n_in,
                              void* d_out, int out_size)
{
    const float* X    = (const float*)d_in[0];
    const float* W    = (const float*)d_in[1];
    const float* bias = (const float*)d_in[2];
    const float* ew   = (const float*)d_in[3];
    const void*  es   = d_in[4];
    const void*  ed   = d_in[5];
    float* out = (float*)d_out;

    // One-time host-side setup (pre-capture correctness call; no device alloc).
    static cudaStream_t s_csr = nullptr, s_agg = nullptr;
    static cudaEvent_t evFork = nullptr, evCSR = nullptr, evG0 = nullptr,
                       evG1 = nullptr, evA = nullptr;
    if (!s_csr) {
        cudaStreamCreateWithFlags(&s_csr, cudaStreamNonBlocking);
        cudaStreamCreateWithFlags(&s_agg, cudaStreamNonBlocking);
        cudaEventCreateWithFlags(&evFork, cudaEventDisableTiming);
        cudaEventCreateWithFlags(&evCSR, cudaEventDisableTiming);
        cudaEventCreateWithFlags(&evG0, cudaEventDisableTiming);
        cudaEventCreateWithFlags(&evG1, cudaEventDisableTiming);
        cudaEventCreateWithFlags(&evA, cudaEventDisableTiming);
        cudaFuncSetAttribute(gemm_mma_kernel,
                             cudaFuncAttributeMaxDynamicSharedMemorySize, GSM);
    }

    // ---- fork ----
    cudaEventRecord(evFork, 0);
    cudaStreamWaitEvent(s_csr, evFork, 0);
    cudaStreamWaitEvent(s_agg, evFork, 0);

    // branch A (s_csr): CSR build (detect folded into hist/place)
    zero_kernel<<<196, 256, 0, s_csr>>>();
    hist_kernel<<<1024, 256, 0, s_csr>>>(ed);
    scan_lookback_kernel<<<SCAN_NB, SCAN_T, 0, s_csr>>>();
    place_kernel<<<1024, 256, 0, s_csr>>>(es, ed, ew);
    cudaEventRecord(evCSR, s_csr);

    // branch B (main): tiny W convert, then GEMM halves (A conv fused in)
    conv_W_kernel<<<256, 256>>>(W);
    gemm_mma_kernel<<<N_PAD / BM, 256, GSM>>>(X, 0);
    cudaEventRecord(evG0, 0);
    gemm_mma_kernel<<<N_PAD / BM, 256, GSM>>>(X, 1);
    cudaEventRecord(evG1, 0);

    // branch C (s_agg): aggregate halves, sequential
    cudaStreamWaitEvent(s_agg, evG0, 0);
    cudaStreamWaitEvent(s_agg, evCSR, 0);
    aggregate_half_kernel<<<N_NODES, 64, 0, s_agg>>>(bias, out, 0);
    cudaStreamWaitEvent(s_agg, evG1, 0);
    aggregate_half_kernel<<<N_NODES, 64, 0, s_agg>>>(bias, out, 64);
    cudaEventRecord(evA, s_agg);

    // main joins
    cudaStreamWaitEvent(0, evA, 0);
}